// round 1
// baseline (speedup 1.0000x reference)
#include <cuda_runtime.h>
#include <cuda_bf16.h>
#include <math.h>

// Problem constants
#define BATCH 4
#define CC 256
#define HH 64
#define WW 64
#define HWN 4096           // H*W
#define NTOK 16384         // B*H*W
#define HEADS 8
#define HDIM 32
#define GROUPS 8
#define CHW (CC*HWN)       // 1048576
#define TOTAL (BATCH*CHW)  // 4194304
#define EPS_GN 1e-5f

// ---------------- scratch (device globals; no allocation allowed) -------------
__device__ float g_Y[(size_t)NTOK * 768];   // token-major [n][768]: q|k|v
__device__ float g_attn[TOTAL];             // NCHW
__device__ float g_pos1[TOTAL];             // NCHW
__device__ float g_U[TOTAL];                // NCHW (attn + pos2)
__device__ float g_Z[TOTAL];                // NCHW (after wp conv)
__device__ float g_stats[3 * BATCH * GROUPS * 2];  // [tensor q/k/z][b][g][mean,rstd]

// ---------------- GEMM 1: Y[n][o] = sum_c W[o][c] * x[b][c][hw] ---------------
// 128x128 tile, BK=16, 256 threads, 8x8 per-thread microtile (split 4+4).
// Epilogue: smem transpose -> token-major store.
__global__ __launch_bounds__(256, 2)
void gemm_qkv_kernel(const float* __restrict__ x,
                     const float* __restrict__ wq,
                     const float* __restrict__ wk,
                     const float* __restrict__ wv) {
    __shared__ float As[16][128];
    __shared__ float Bs[16][128];
    __shared__ float tb[32][129];

    const int bx = blockIdx.x;       // n tile (0..31)
    const int by = blockIdx.y;       // o tile (0..5) -> 768 channels
    const int b  = blockIdx.z;       // batch

    const float* W = (by < 2) ? wq : ((by < 4) ? wk : wv);
    const int wrow0 = (by & 1) * 128;
    const float* Xb = x + (size_t)b * CHW + bx * 128;

    const int tid = threadIdx.x;
    const int tx = tid & 15;
    const int ty = tid >> 4;

    float acc[8][8];
#pragma unroll
    for (int i = 0; i < 8; i++)
#pragma unroll
        for (int j = 0; j < 8; j++) acc[i][j] = 0.f;

    for (int k0 = 0; k0 < 256; k0 += 16) {
#pragma unroll
        for (int r = 0; r < 2; r++) {
            int f = tid + r * 256;               // 0..511 float4 slots
            int row = f >> 2, kk = (f & 3) << 2; // A: 128 rows x 16 k
            float4 av = *(const float4*)(W + (size_t)(wrow0 + row) * 256 + k0 + kk);
            As[kk + 0][row] = av.x; As[kk + 1][row] = av.y;
            As[kk + 2][row] = av.z; As[kk + 3][row] = av.w;
            int kb = f >> 5, nn = (f & 31) << 2; // B: 16 k x 128 n
            float4 bv = *(const float4*)(Xb + (size_t)(k0 + kb) * HWN + nn);
            *(float4*)&Bs[kb][nn] = bv;
        }
        __syncthreads();
#pragma unroll
        for (int k = 0; k < 16; k++) {
            float a[8], bb[8];
            *(float4*)&a[0]  = *(float4*)&As[k][ty * 4];
            *(float4*)&a[4]  = *(float4*)&As[k][64 + ty * 4];
            *(float4*)&bb[0] = *(float4*)&Bs[k][tx * 4];
            *(float4*)&bb[4] = *(float4*)&Bs[k][64 + tx * 4];
#pragma unroll
            for (int i = 0; i < 8; i++)
#pragma unroll
                for (int j = 0; j < 8; j++) acc[i][j] = fmaf(a[i], bb[j], acc[i][j]);
        }
        __syncthreads();
    }

    // epilogue: transpose 32-row chunks into token-major g_Y
    const size_t nbase = (size_t)b * HWN + bx * 128;
    const int obase = by * 128;
#pragma unroll
    for (int c0 = 0; c0 < 128; c0 += 32) {
        const int mg = c0 >> 6;
        const int tyl0 = (c0 & 63) >> 2;
        __syncthreads();
        if (ty >= tyl0 && ty < tyl0 + 8) {
#pragma unroll
            for (int i = 0; i < 4; i++) {
                int rl = (ty - tyl0) * 4 + i;
#pragma unroll
                for (int jg = 0; jg < 2; jg++)
#pragma unroll
                    for (int j = 0; j < 4; j++)
                        tb[rl][jg * 64 + tx * 4 + j] = acc[mg * 4 + i][jg * 4 + j];
            }
        }
        __syncthreads();
#pragma unroll
        for (int p = 0; p < 16; p++) {
            int nn = (tid >> 5) + p * 8;
            int ol = tid & 31;
            g_Y[(nbase + nn) * 768 + obase + c0 + ol] = tb[ol][nn];
        }
    }
}

// ---------------- GN stats over token-major Y (for q: off=0, k: off=256) ------
__global__ void gn_stats_tok_kernel(int toff, int slot) {
    const int b = blockIdx.x >> 3;
    const int g = blockIdx.x & 7;
    const float* base = g_Y + (size_t)b * HWN * 768 + toff + g * 32;
    float s = 0.f, s2 = 0.f;
    for (int i = threadIdx.x; i < HWN * 32; i += 256) {
        int n = i >> 5, c = i & 31;
        float v = base[(size_t)n * 768 + c];
        s += v; s2 += v * v;
    }
    __shared__ float red[512];
    red[threadIdx.x] = s; red[256 + threadIdx.x] = s2;
    __syncthreads();
    for (int st = 128; st > 0; st >>= 1) {
        if (threadIdx.x < st) {
            red[threadIdx.x] += red[threadIdx.x + st];
            red[256 + threadIdx.x] += red[256 + threadIdx.x + st];
        }
        __syncthreads();
    }
    if (threadIdx.x == 0) {
        const float inv = 1.f / (float)(HWN * 32);
        float mean = red[0] * inv;
        float var = red[256] * inv - mean * mean;
        g_stats[(slot * 32 + blockIdx.x) * 2 + 0] = mean;
        g_stats[(slot * 32 + blockIdx.x) * 2 + 1] = rsqrtf(var + EPS_GN);
    }
}

// ---------------- GN stats over NCHW g_Z (slot 2) ----------------------------
__global__ void gn_stats_nchw_kernel() {
    const int b = blockIdx.x >> 3;
    const int g = blockIdx.x & 7;
    const float* base = g_Z + ((size_t)b * CC + g * 32) * HWN;
    float s = 0.f, s2 = 0.f;
    for (int i = threadIdx.x; i < 32 * HWN; i += 256) {
        float v = base[i];
        s += v; s2 += v * v;
    }
    __shared__ float red[512];
    red[threadIdx.x] = s; red[256 + threadIdx.x] = s2;
    __syncthreads();
    for (int st = 128; st > 0; st >>= 1) {
        if (threadIdx.x < st) {
            red[threadIdx.x] += red[threadIdx.x + st];
            red[256 + threadIdx.x] += red[256 + threadIdx.x + st];
        }
        __syncthreads();
    }
    if (threadIdx.x == 0) {
        const float inv = 1.f / (float)(HWN * 32);
        float mean = red[0] * inv;
        float var = red[256] * inv - mean * mean;
        g_stats[(2 * 32 + blockIdx.x) * 2 + 0] = mean;
        g_stats[(2 * 32 + blockIdx.x) * 2 + 1] = rsqrtf(var + EPS_GN);
    }
}

// ---------------- attention: warp per token, lane per head-dim ----------------
__global__ __launch_bounds__(1024)
void attn_kernel(const float* __restrict__ gq_g, const float* __restrict__ gq_b,
                 const float* __restrict__ gk_g, const float* __restrict__ gk_b) {
    __shared__ float so[256][33];
    const int warp = threadIdx.x >> 5;
    const int lane = threadIdx.x & 31;
    const int n = blockIdx.x * 32 + warp;
    const int b = n >> 12;
    const float* yr = g_Y + (size_t)n * 768;
    const float scale = 0.17677669529663687f; // 1/sqrt(32)

#pragma unroll 1
    for (int h = 0; h < 8; h++) {
        const int c = h * 32 + lane;
        float q = yr[c];
        float k = yr[256 + c];
        float v = yr[512 + c];
        const int qi = ((0 * 4 + b) * 8 + h) * 2;
        const int ki = ((1 * 4 + b) * 8 + h) * 2;
        q = (q - g_stats[qi]) * g_stats[qi + 1] * gq_g[c] + gq_b[c];
        k = (k - g_stats[ki]) * g_stats[ki + 1] * gk_g[c] + gk_b[c];

        // L2 normalize over the 32 lanes (one head)
        float sq = q * q;
        float sk = k * k;
#pragma unroll
        for (int off = 16; off > 0; off >>= 1) {
            sq += __shfl_xor_sync(0xffffffffu, sq, off);
            sk += __shfl_xor_sync(0xffffffffu, sk, off);
        }
        q *= 1.f / fmaxf(sqrtf(sq), 1e-12f);
        k *= 1.f / fmaxf(sqrtf(sk), 1e-12f);

        const float s = q * scale;
        float num = 0.f, den = 0.f;
#pragma unroll
        for (int e = 0; e < 32; e++) {
            float ke = __shfl_sync(0xffffffffu, k, e);
            float ve = __shfl_sync(0xffffffffu, v, e);
            float w = __expf(s * ke);
            den += w;
            num = fmaf(w, ve, num);
        }
        so[c][warp] = num / den;
    }
    __syncthreads();
    const int hw0 = (blockIdx.x * 32) & (HWN - 1);
    float* ob = g_attn + (size_t)b * CHW + hw0;
    for (int i = threadIdx.x; i < 256 * 32; i += 1024) {
        int c = i >> 5, px = i & 31;
        ob[(size_t)c * HWN + px] = so[c][px];
    }
}

// ---------------- depthwise conv 3x3 + GeLU (exact) --------------------------
__global__ void dwconv1_gelu_kernel(const float* __restrict__ x,
                                    const float* __restrict__ dw,
                                    const float* __restrict__ db) {
    int idx = blockIdx.x * 256 + threadIdx.x;
    if (idx >= TOTAL) return;
    const int px = idx & 63;
    const int py = (idx >> 6) & 63;
    const int c = (idx >> 12) & 255;
    const float* xb = x + (size_t)(idx >> 12) * HWN;
    const float* wc = dw + c * 9;
    float acc = db[c];
#pragma unroll
    for (int dy = -1; dy <= 1; dy++) {
        int yy = py + dy;
        if ((unsigned)yy > 63u) continue;
#pragma unroll
        for (int dx = -1; dx <= 1; dx++) {
            int xx = px + dx;
            if ((unsigned)xx > 63u) continue;
            acc = fmaf(xb[yy * 64 + xx], wc[(dy + 1) * 3 + (dx + 1)], acc);
        }
    }
    g_pos1[idx] = 0.5f * acc * (1.f + erff(acc * 0.70710678118654752f));
}

// pos2 = dwconv3x3(pos1, dw2)+db2 ; U = pos2 + attn
__global__ void dwconv2_add_kernel(const float* __restrict__ dw,
                                   const float* __restrict__ db) {
    int idx = blockIdx.x * 256 + threadIdx.x;
    if (idx >= TOTAL) return;
    const int px = idx & 63;
    const int py = (idx >> 6) & 63;
    const int c = (idx >> 12) & 255;
    const float* xb = g_pos1 + (size_t)(idx >> 12) * HWN;
    const float* wc = dw + c * 9;
    float acc = db[c];
#pragma unroll
    for (int dy = -1; dy <= 1; dy++) {
        int yy = py + dy;
        if ((unsigned)yy > 63u) continue;
#pragma unroll
        for (int dx = -1; dx <= 1; dx++) {
            int xx = px + dx;
            if ((unsigned)xx > 63u) continue;
            acc = fmaf(xb[yy * 64 + xx], wc[(dy + 1) * 3 + (dx + 1)], acc);
        }
    }
    g_U[idx] = acc + g_attn[idx];
}

// ---------------- GEMM 2: Z[b][o][hw] = sum_c wp[o][c] U[b][c][hw] + bp[o] ----
__global__ __launch_bounds__(256, 2)
void gemm_out_kernel(const float* __restrict__ wp, const float* __restrict__ bp) {
    __shared__ float As[16][128];
    __shared__ float Bs[16][128];

    const int bx = blockIdx.x;   // n tile (0..31)
    const int by = blockIdx.y;   // o tile (0..1)
    const int b  = blockIdx.z;

    const int wrow0 = by * 128;
    const float* Xb = g_U + (size_t)b * CHW + bx * 128;

    const int tid = threadIdx.x;
    const int tx = tid & 15;
    const int ty = tid >> 4;

    float acc[8][8];
#pragma unroll
    for (int i = 0; i < 8; i++)
#pragma unroll
        for (int j = 0; j < 8; j++) acc[i][j] = 0.f;

    for (int k0 = 0; k0 < 256; k0 += 16) {
#pragma unroll
        for (int r = 0; r < 2; r++) {
            int f = tid + r * 256;
            int row = f >> 2, kk = (f & 3) << 2;
            float4 av = *(const float4*)(wp + (size_t)(wrow0 + row) * 256 + k0 + kk);
            As[kk + 0][row] = av.x; As[kk + 1][row] = av.y;
            As[kk + 2][row] = av.z; As[kk + 3][row] = av.w;
            int kb = f >> 5, nn = (f & 31) << 2;
            float4 bv = *(const float4*)(Xb + (size_t)(k0 + kb) * HWN + nn);
            *(float4*)&Bs[kb][nn] = bv;
        }
        __syncthreads();
#pragma unroll
        for (int k = 0; k < 16; k++) {
            float a[8], bb[8];
            *(float4*)&a[0]  = *(float4*)&As[k][ty * 4];
            *(float4*)&a[4]  = *(float4*)&As[k][64 + ty * 4];
            *(float4*)&bb[0] = *(float4*)&Bs[k][tx * 4];
            *(float4*)&bb[4] = *(float4*)&Bs[k][64 + tx * 4];
#pragma unroll
            for (int i = 0; i < 8; i++)
#pragma unroll
                for (int j = 0; j < 8; j++) acc[i][j] = fmaf(a[i], bb[j], acc[i][j]);
        }
        __syncthreads();
    }

#pragma unroll
    for (int mg = 0; mg < 2; mg++)
#pragma unroll
        for (int i = 0; i < 4; i++) {
            int o = wrow0 + mg * 64 + ty * 4 + i;
            float bias = bp[o];
            float* zr = g_Z + ((size_t)b * CC + o) * HWN + bx * 128;
#pragma unroll
            for (int jg = 0; jg < 2; jg++) {
                float4 v;
                v.x = acc[mg * 4 + i][jg * 4 + 0] + bias;
                v.y = acc[mg * 4 + i][jg * 4 + 1] + bias;
                v.z = acc[mg * 4 + i][jg * 4 + 2] + bias;
                v.w = acc[mg * 4 + i][jg * 4 + 3] + bias;
                *(float4*)(zr + jg * 64 + tx * 4) = v;
            }
        }
}

// ---------------- final GN apply ---------------------------------------------
__global__ void gn_apply_kernel(const float* __restrict__ gamma,
                                const float* __restrict__ beta,
                                float* __restrict__ out) {
    int idx = blockIdx.x * 256 + threadIdx.x;
    if (idx >= TOTAL) return;
    const int c = (idx >> 12) & 255;
    const int b = idx >> 20;
    const int g = c >> 5;
    const int si = (2 * 32 + b * 8 + g) * 2;
    out[idx] = (g_Z[idx] - g_stats[si]) * g_stats[si + 1] * gamma[c] + beta[c];
}

// ---------------- launcher ----------------------------------------------------
extern "C" void kernel_launch(void* const* d_in, const int* in_sizes, int n_in,
                              void* d_out, int out_size) {
    const float* x        = (const float*)d_in[0];
    const float* wq       = (const float*)d_in[1];
    const float* gq_gamma = (const float*)d_in[2];
    const float* gq_beta  = (const float*)d_in[3];
    const float* wk       = (const float*)d_in[4];
    const float* gk_gamma = (const float*)d_in[5];
    const float* gk_beta  = (const float*)d_in[6];
    const float* wv       = (const float*)d_in[7];
    const float* wp       = (const float*)d_in[8];
    const float* bp       = (const float*)d_in[9];
    const float* gp_gamma = (const float*)d_in[10];
    const float* gp_beta  = (const float*)d_in[11];
    const float* dw1      = (const float*)d_in[12];
    const float* db1      = (const float*)d_in[13];
    const float* dw2      = (const float*)d_in[14];
    const float* db2      = (const float*)d_in[15];
    float* out = (float*)d_out;

    // 1. QKV GEMM -> token-major g_Y
    gemm_qkv_kernel<<<dim3(32, 6, BATCH), 256>>>(x, wq, wk, wv);
    // 2. GN stats for q and k
    gn_stats_tok_kernel<<<32, 256>>>(0, 0);
    gn_stats_tok_kernel<<<32, 256>>>(256, 1);
    // 3. attention -> g_attn (NCHW)
    attn_kernel<<<512, 1024>>>(gq_gamma, gq_beta, gk_gamma, gk_beta);
    // 4. positional path
    dwconv1_gelu_kernel<<<TOTAL / 256, 256>>>(x, dw1, db1);
    dwconv2_add_kernel<<<TOTAL / 256, 256>>>(dw2, db2);
    // 5. output projection
    gemm_out_kernel<<<dim3(32, 2, BATCH), 256>>>(wp, bp);
    // 6. final group norm
    gn_stats_nchw_kernel<<<32, 256>>>();
    gn_apply_kernel<<<TOTAL / 256, 256>>>(gp_gamma, gp_beta, out);
}

// round 3
// speedup vs baseline: 1.2556x; 1.2556x over previous
#include <cuda_runtime.h>
#include <cuda_bf16.h>
#include <math.h>
#include <stdint.h>

#define BATCH 4
#define CCH 256
#define HWN 4096
#define NTOK 16384          // BATCH*HWN
#define CHW (CCH*HWN)
#define TOTAL (BATCH*CHW)
#define EPS_GN 1e-5f
#define LDT 40              // padded smem row length (bf16) for 32-wide K tile

// ---------------- scratch (device globals) ------------------------------------
__device__ float g_Y[(size_t)768 * NTOK];          // [768][16384] q|k|v channel-major
__device__ float g_attn[(size_t)CCH * NTOK];       // [256][16384] channel-major
__device__ float g_pos1[TOTAL];                    // NCHW
__device__ float g_U[(size_t)CCH * NTOK];          // [256][16384] channel-major
__device__ float g_Z[(size_t)CCH * NTOK];          // [256][16384] channel-major
__device__ float g_stats[3 * 32 * 2];              // [slot q/k/z][b*8+g][mean,rstd]
__device__ __nv_bfloat16 g_Whi[768 * 256], g_Wlo[768 * 256];
__device__ __nv_bfloat16 g_Wphi[256 * 256], g_Wplo[256 * 256];
__device__ __nv_bfloat16 g_Xhi[(size_t)NTOK * 256], g_Xlo[(size_t)NTOK * 256];
__device__ __nv_bfloat16 g_Uhi[(size_t)NTOK * 256], g_Ulo[(size_t)NTOK * 256];

// ---------------- helpers ------------------------------------------------------
__device__ __forceinline__ uint32_t smem_u32(const void* p) {
    return (uint32_t)__cvta_generic_to_shared(p);
}
__device__ __forceinline__ unsigned short f2bf_us(float v) {
    __nv_bfloat16 b = __float2bfloat16(v);
    return *reinterpret_cast<unsigned short*>(&b);
}
__device__ __forceinline__ void cp_async16(uint32_t s, const void* g) {
    asm volatile("cp.async.cg.shared.global [%0], [%1], 16;" :: "r"(s), "l"(g));
}
__device__ __forceinline__ void cp_commit() {
    asm volatile("cp.async.commit_group;");
}
__device__ __forceinline__ void ldsm_x4(uint32_t* r, uint32_t a) {
    asm volatile("ldmatrix.sync.aligned.m8n8.x4.shared.b16 {%0,%1,%2,%3}, [%4];"
                 : "=r"(r[0]), "=r"(r[1]), "=r"(r[2]), "=r"(r[3]) : "r"(a));
}
__device__ __forceinline__ void ldsm_x2(uint32_t* r, uint32_t a) {
    asm volatile("ldmatrix.sync.aligned.m8n8.x2.shared.b16 {%0,%1}, [%2];"
                 : "=r"(r[0]), "=r"(r[1]) : "r"(a));
}
__device__ __forceinline__ void mma_bf16(float* c, const uint32_t* a, const uint32_t* b) {
    asm volatile(
        "mma.sync.aligned.m16n8k16.row.col.f32.bf16.bf16.f32 "
        "{%0,%1,%2,%3}, {%4,%5,%6,%7}, {%8,%9}, {%0,%1,%2,%3};"
        : "+f"(c[0]), "+f"(c[1]), "+f"(c[2]), "+f"(c[3])
        : "r"(a[0]), "r"(a[1]), "r"(a[2]), "r"(a[3]), "r"(b[0]), "r"(b[1]));
}

// ---------------- W -> bf16 hi/lo (K-major already) ---------------------------
__global__ void convert_w_kernel(const float* __restrict__ wq, const float* __restrict__ wk,
                                 const float* __restrict__ wv, const float* __restrict__ wp) {
    int i = blockIdx.x * 256 + threadIdx.x;  // 0..262143
    float v;
    __nv_bfloat16 *hi, *lo;
    int o;
    if (i < 65536)        { v = wq[i];          o = i;          hi = g_Whi;  lo = g_Wlo; }
    else if (i < 131072)  { v = wk[i - 65536];  o = i;          hi = g_Whi;  lo = g_Wlo; }
    else if (i < 196608)  { v = wv[i - 131072]; o = i;          hi = g_Whi;  lo = g_Wlo; }
    else                  { v = wp[i - 196608]; o = i - 196608; hi = g_Wphi; lo = g_Wplo; }
    __nv_bfloat16 h = __float2bfloat16(v);
    hi[o] = h;
    lo[o] = __float2bfloat16(v - __bfloat162float(h));
}

// ---------------- transpose [c][hw] fp32 -> token-major bf16 hi/lo -------------
__global__ void transpose_convert_kernel(const float* __restrict__ src, int c_stride, int b_stride,
                                         __nv_bfloat16* __restrict__ dhi,
                                         __nv_bfloat16* __restrict__ dlo) {
    __shared__ float t[32][33];
    const int hw0 = blockIdx.x * 32, c0 = blockIdx.y * 32, b = blockIdx.z;
    const int tid = threadIdx.x;
    const int rl = tid >> 3, q = tid & 7;
    float4 v = *(const float4*)(src + (size_t)b * b_stride + (size_t)(c0 + rl) * c_stride + hw0 + q * 4);
    t[rl][q * 4 + 0] = v.x; t[rl][q * 4 + 1] = v.y;
    t[rl][q * 4 + 2] = v.z; t[rl][q * 4 + 3] = v.w;
    __syncthreads();
    const int n = b * HWN + hw0 + rl;
    ushort4 hs, ls;
    float f0 = t[q * 4 + 0][rl], f1 = t[q * 4 + 1][rl];
    float f2 = t[q * 4 + 2][rl], f3 = t[q * 4 + 3][rl];
    hs.x = f2bf_us(f0); hs.y = f2bf_us(f1); hs.z = f2bf_us(f2); hs.w = f2bf_us(f3);
    ls.x = f2bf_us(f0 - __bfloat162float(__float2bfloat16(f0)));
    ls.y = f2bf_us(f1 - __bfloat162float(__float2bfloat16(f1)));
    ls.z = f2bf_us(f2 - __bfloat162float(__float2bfloat16(f2)));
    ls.w = f2bf_us(f3 - __bfloat162float(__float2bfloat16(f3)));
    *(ushort4*)(dhi + (size_t)n * 256 + c0 + q * 4) = hs;
    *(ushort4*)(dlo + (size_t)n * 256 + c0 + q * 4) = ls;
}

// ---------------- mma.sync GEMM: out[m][n] = sum_k A[m][k]*B[n][k] -------------
// bf16 2-term split: Ahi*Bhi + Ahi*Blo + Alo*Bhi as K_eff = 3*256 = 768.
// 128x128 tile, BK=32, 8 warps (2x4), warp tile 64x32, cp.async double buffer.
__global__ __launch_bounds__(256) void mma_gemm_kernel(
    const __nv_bfloat16* __restrict__ Ahi, const __nv_bfloat16* __restrict__ Alo,
    const __nv_bfloat16* __restrict__ Bhi, const __nv_bfloat16* __restrict__ Blo,
    float* __restrict__ out, const float* __restrict__ bias) {
    __shared__ __nv_bfloat16 As[2][128 * LDT];
    __shared__ __nv_bfloat16 Bs[2][128 * LDT];
    const int tid = threadIdx.x;
    const int lane = tid & 31;
    const int wid = tid >> 5;
    const int wm = wid >> 2;          // 0..1
    const int wn = wid & 3;           // 0..3
    const int m0 = blockIdx.y * 128;
    const int n0 = blockIdx.x * 128;
    const int NITER = 24;             // 3 passes x 8

    float acc[4][4][4];
#pragma unroll
    for (int i = 0; i < 4; i++)
#pragma unroll
        for (int j = 0; j < 4; j++)
#pragma unroll
            for (int r = 0; r < 4; r++) acc[i][j][r] = 0.f;

    // loader lambda (inlined manually): loads tile kc into buffer buf
    const int lrow = tid >> 1;            // 0..127 (2 chunks per row handled below)
    const int lch2 = (tid & 1) * 2;       // chunk pairs {0,1} or {2,3}

#define LOAD_TILE(buf, kc)                                                              \
    do {                                                                                \
        int p = (kc) >> 3, k0 = ((kc) & 7) * 32;                                        \
        const __nv_bfloat16* ga = ((p == 2) ? Alo : Ahi) + (size_t)(m0 + lrow) * 256 + k0; \
        const __nv_bfloat16* gb = ((p == 1) ? Blo : Bhi) + (size_t)(n0 + lrow) * 256 + k0; \
        uint32_t sa = smem_u32(&As[buf][lrow * LDT + lch2 * 8]);                        \
        uint32_t sb = smem_u32(&Bs[buf][lrow * LDT + lch2 * 8]);                        \
        cp_async16(sa,      ga + lch2 * 8);                                             \
        cp_async16(sa + 16, ga + lch2 * 8 + 8);                                         \
        cp_async16(sb,      gb + lch2 * 8);                                             \
        cp_async16(sb + 16, gb + lch2 * 8 + 8);                                         \
        cp_commit();                                                                    \
    } while (0)

    LOAD_TILE(0, 0);

    int buf = 0;
    for (int kc = 0; kc < NITER; kc++) {
        if (kc + 1 < NITER) {
            LOAD_TILE(buf ^ 1, kc + 1);
            asm volatile("cp.async.wait_group 1;");
        } else {
            asm volatile("cp.async.wait_group 0;");
        }
        __syncthreads();

        // compute from As[buf], Bs[buf]
#pragma unroll
        for (int ks = 0; ks < 2; ks++) {
            uint32_t afr[4][4];
#pragma unroll
            for (int i = 0; i < 4; i++) {
                uint32_t a = smem_u32(&As[buf][(wm * 64 + i * 16 + (lane & 15)) * LDT +
                                              ((lane >> 4) * 8 + ks * 16)]);
                ldsm_x4(afr[i], a);
            }
            uint32_t bfr[4][2];
#pragma unroll
            for (int j = 0; j < 4; j++) {
                int l2 = lane & 15;
                uint32_t a = smem_u32(&Bs[buf][(wn * 32 + j * 8 + (l2 & 7)) * LDT +
                                              (((l2 >> 3) & 1) * 8 + ks * 16)]);
                ldsm_x2(bfr[j], a);
            }
#pragma unroll
            for (int i = 0; i < 4; i++)
#pragma unroll
                for (int j = 0; j < 4; j++) mma_bf16(acc[i][j], afr[i], bfr[j]);
        }
        __syncthreads();
        buf ^= 1;
    }
#undef LOAD_TILE

    // epilogue: direct float2 stores, channel-major out [m][NTOK]
#pragma unroll
    for (int i = 0; i < 4; i++) {
        const int row = m0 + wm * 64 + i * 16 + (lane >> 2);
        const float b0v = bias ? bias[row] : 0.f;
        const float b1v = bias ? bias[row + 8] : 0.f;
#pragma unroll
        for (int j = 0; j < 4; j++) {
            const int col = n0 + wn * 32 + j * 8 + (lane & 3) * 2;
            float2 v0 = make_float2(acc[i][j][0] + b0v, acc[i][j][1] + b0v);
            float2 v1 = make_float2(acc[i][j][2] + b1v, acc[i][j][3] + b1v);
            *(float2*)(out + (size_t)row * NTOK + col) = v0;
            *(float2*)(out + (size_t)(row + 8) * NTOK + col) = v1;
        }
    }
}

// ---------------- GN stats over channel-major [.][16384] -----------------------
__global__ void gn_stats_cm_kernel(const float* __restrict__ base, int slot) {
    const int b = blockIdx.x >> 3;
    const int g = blockIdx.x & 7;
    const float* p = base + (size_t)(g * 32) * NTOK + b * HWN;
    float s = 0.f, s2 = 0.f;
    for (int i = threadIdx.x; i < 32 * 1024; i += 256) {
        int r = i >> 10, c4 = i & 1023;
        float4 v = *(const float4*)(p + (size_t)r * NTOK + c4 * 4);
        s += v.x + v.y + v.z + v.w;
        s2 += v.x * v.x + v.y * v.y + v.z * v.z + v.w * v.w;
    }
    __shared__ float red[512];
    red[threadIdx.x] = s; red[256 + threadIdx.x] = s2;
    __syncthreads();
    for (int st = 128; st > 0; st >>= 1) {
        if (threadIdx.x < st) {
            red[threadIdx.x] += red[threadIdx.x + st];
            red[256 + threadIdx.x] += red[256 + threadIdx.x + st];
        }
        __syncthreads();
    }
    if (threadIdx.x == 0) {
        const float inv = 1.f / 131072.f;
        float mean = red[0] * inv;
        float var = red[256] * inv - mean * mean;
        g_stats[(slot * 32 + blockIdx.x) * 2 + 0] = mean;
        g_stats[(slot * 32 + blockIdx.x) * 2 + 1] = rsqrtf(var + EPS_GN);
    }
}

// ---------------- attention: 32 tokens/block, warp-per-token, smem k/v ---------
__global__ __launch_bounds__(1024) void attn_kernel(
    const float* __restrict__ gqg, const float* __restrict__ gqb,
    const float* __restrict__ gkg, const float* __restrict__ gkb) {
    extern __shared__ float smf[];
    float* smq = smf;                 // [256][33]
    float* smk = smf + 256 * 33;
    float* smv = smf + 2 * 256 * 33;
    float* knb = smf + 3 * 256 * 33;  // [32 warps][32]
    const int tid = threadIdx.x;
    const int warp = tid >> 5;
    const int lane = tid & 31;
    const int n0 = blockIdx.x * 32;
    const int b = n0 >> 12;

#pragma unroll
    for (int r = 0; r < 6; r++) {
        const int tens = r >> 1;
        const int slot = tid + r * 1024;
        const int row = (slot >> 3) & 255;
        const int q = slot & 7;
        float4 v = *(const float4*)(g_Y + (size_t)(tens * 256 + row) * NTOK + n0 + q * 4);
        float* dst = smf + tens * (256 * 33) + row * 33 + q * 4;
        dst[0] = v.x; dst[1] = v.y; dst[2] = v.z; dst[3] = v.w;
    }
    __syncthreads();

    const float scale_l2e = 0.17677669529663687f * 1.4426950408889634f;
    float oacc[8];
#pragma unroll 1
    for (int h = 0; h < 8; h++) {
        const int c = h * 32 + lane;
        float q = smq[c * 33 + warp];
        float k = smk[c * 33 + warp];
        const int qi = (b * 8 + h) * 2;
        const int ki = (32 + b * 8 + h) * 2;
        q = (q - g_stats[qi]) * g_stats[qi + 1] * gqg[c] + gqb[c];
        k = (k - g_stats[ki]) * g_stats[ki + 1] * gkg[c] + gkb[c];
        float sq = q * q, sk = k * k;
#pragma unroll
        for (int off = 16; off > 0; off >>= 1) {
            sq += __shfl_xor_sync(0xffffffffu, sq, off);
            sk += __shfl_xor_sync(0xffffffffu, sk, off);
        }
        const float qn = q / fmaxf(sqrtf(sq), 1e-12f);
        const float kn = k / fmaxf(sqrtf(sk), 1e-12f);
        __syncwarp();
        knb[warp * 32 + lane] = kn;
        __syncwarp();
        const float s2 = qn * scale_l2e;
        float num = 0.f, den = 0.f;
#pragma unroll
        for (int e = 0; e < 32; e++) {
            float ke = knb[warp * 32 + e];
            float ve = smv[(h * 32 + e) * 33 + warp];
            float t = s2 * ke;
            float w;
            asm("ex2.approx.f32 %0, %1;" : "=f"(w) : "f"(t));
            den += w;
            num = fmaf(w, ve, num);
        }
        oacc[h] = num / den;
    }
#pragma unroll
    for (int h = 0; h < 8; h++) smq[(h * 32 + lane) * 33 + warp] = oacc[h];
    __syncthreads();
#pragma unroll
    for (int it = 0; it < 8; it++) {
        int idx = tid + it * 1024;
        int c = idx >> 5, j = idx & 31;
        g_attn[(size_t)c * NTOK + n0 + j] = smq[c * 33 + j];
    }
}

// ---------------- depthwise conv 3x3 + GeLU (exact) ----------------------------
__global__ void dwconv1_gelu_kernel(const float* __restrict__ x,
                                    const float* __restrict__ dw,
                                    const float* __restrict__ db) {
    int idx = blockIdx.x * 256 + threadIdx.x;
    if (idx >= TOTAL) return;
    const int px = idx & 63;
    const int py = (idx >> 6) & 63;
    const int c = (idx >> 12) & 255;
    const float* xb = x + (size_t)(idx >> 12) * HWN;
    const float* wc = dw + c * 9;
    float acc = db[c];
#pragma unroll
    for (int dy = -1; dy <= 1; dy++) {
        int yy = py + dy;
        if ((unsigned)yy > 63u) continue;
#pragma unroll
        for (int dx = -1; dx <= 1; dx++) {
            int xx = px + dx;
            if ((unsigned)xx > 63u) continue;
            acc = fmaf(xb[yy * 64 + xx], wc[(dy + 1) * 3 + (dx + 1)], acc);
        }
    }
    g_pos1[idx] = 0.5f * acc * (1.f + erff(acc * 0.70710678118654752f));
}

// pos2 = dwconv3x3(pos1) + db2; U = pos2 + attn (U channel-major [c][n])
__global__ void dwconv2_add_kernel(const float* __restrict__ dw,
                                   const float* __restrict__ db) {
    int idx = blockIdx.x * 256 + threadIdx.x;
    if (idx >= TOTAL) return;
    const int px = idx & 63;
    const int py = (idx >> 6) & 63;
    const int c = (idx >> 12) & 255;
    const int b = idx >> 20;
    const float* xb = g_pos1 + (size_t)(idx >> 12) * HWN;
    const float* wc = dw + c * 9;
    float acc = db[c];
#pragma unroll
    for (int dy = -1; dy <= 1; dy++) {
        int yy = py + dy;
        if ((unsigned)yy > 63u) continue;
#pragma unroll
        for (int dx = -1; dx <= 1; dx++) {
            int xx = px + dx;
            if ((unsigned)xx > 63u) continue;
            acc = fmaf(xb[yy * 64 + xx], wc[(dy + 1) * 3 + (dx + 1)], acc);
        }
    }
    const size_t cn = (size_t)c * NTOK + b * HWN + (idx & 4095);
    g_U[cn] = acc + g_attn[cn];
}

// ---------------- final GN apply (channel-major in, NCHW out) ------------------
__global__ void gn_apply_kernel(const float* __restrict__ gamma,
                                const float* __restrict__ beta,
                                float* __restrict__ out) {
    int idx = blockIdx.x * 256 + threadIdx.x;  // over 256*16384
    const int c = idx >> 14;
    const int n = idx & 16383;
    const int b = n >> 12;
    const int g = c >> 5;
    const int si = (2 * 32 + b * 8 + g) * 2;
    float v = (g_Z[idx] - g_stats[si]) * g_stats[si + 1] * gamma[c] + beta[c];
    out[(size_t)b * CHW + (size_t)c * HWN + (n & 4095)] = v;
}

// ---------------- launcher -----------------------------------------------------
extern "C" void kernel_launch(void* const* d_in, const int* in_sizes, int n_in,
                              void* d_out, int out_size) {
    const float* x        = (const float*)d_in[0];
    const float* wq       = (const float*)d_in[1];
    const float* gq_gamma = (const float*)d_in[2];
    const float* gq_beta  = (const float*)d_in[3];
    const float* wk       = (const float*)d_in[4];
    const float* gk_gamma = (const float*)d_in[5];
    const float* gk_beta  = (const float*)d_in[6];
    const float* wv       = (const float*)d_in[7];
    const float* wp       = (const float*)d_in[8];
    const float* bp       = (const float*)d_in[9];
    const float* gp_gamma = (const float*)d_in[10];
    const float* gp_beta  = (const float*)d_in[11];
    const float* dw1      = (const float*)d_in[12];
    const float* db1      = (const float*)d_in[13];
    const float* dw2      = (const float*)d_in[14];
    const float* db2      = (const float*)d_in[15];
    float* out = (float*)d_out;

    static bool attr_set = false;
    if (!attr_set) {
        cudaFuncSetAttribute(attn_kernel, cudaFuncAttributeMaxDynamicSharedMemorySize, 105472);
        attr_set = true;
    }

    float *g_Y_p, *g_U_p, *g_Z_p;
    __nv_bfloat16 *whi, *wlo, *wphi, *wplo, *xhi, *xlo, *uhi, *ulo;
    cudaGetSymbolAddress((void**)&g_Y_p, g_Y);
    cudaGetSymbolAddress((void**)&g_U_p, g_U);
    cudaGetSymbolAddress((void**)&g_Z_p, g_Z);
    cudaGetSymbolAddress((void**)&whi, g_Whi);
    cudaGetSymbolAddress((void**)&wlo, g_Wlo);
    cudaGetSymbolAddress((void**)&wphi, g_Wphi);
    cudaGetSymbolAddress((void**)&wplo, g_Wplo);
    cudaGetSymbolAddress((void**)&xhi, g_Xhi);
    cudaGetSymbolAddress((void**)&xlo, g_Xlo);
    cudaGetSymbolAddress((void**)&uhi, g_Uhi);
    cudaGetSymbolAddress((void**)&ulo, g_Ulo);

    // 1. weight + input conversion
    convert_w_kernel<<<1024, 256>>>(wq, wk, wv, wp);
    transpose_convert_kernel<<<dim3(128, 8, BATCH), 256>>>(x, HWN, CHW, xhi, xlo);
    // 2. QKV GEMM (mma.sync bf16 split) -> g_Y [768][16384]
    mma_gemm_kernel<<<dim3(128, 6), 256>>>(whi, wlo, xhi, xlo, g_Y_p, nullptr);
    // 3. GN stats for q, k
    gn_stats_cm_kernel<<<32, 256>>>(g_Y_p, 0);
    gn_stats_cm_kernel<<<32, 256>>>(g_Y_p + (size_t)256 * NTOK, 1);
    // 4. attention -> g_attn [c][n]
    attn_kernel<<<512, 1024, 105472>>>(gq_gamma, gq_beta, gk_gamma, gk_beta);
    // 5. positional path
    dwconv1_gelu_kernel<<<TOTAL / 256, 256>>>(x, dw1, db1);
    dwconv2_add_kernel<<<TOTAL / 256, 256>>>(dw2, db2);
    // 6. U -> token-major bf16, output projection GEMM -> g_Z [256][16384]
    transpose_convert_kernel<<<dim3(128, 8, BATCH), 256>>>(g_U_p, NTOK, HWN, uhi, ulo);
    mma_gemm_kernel<<<dim3(128, 2), 256>>>(wphi, wplo, uhi, ulo, g_Z_p, bp);
    // 7. final group norm
    gn_stats_cm_kernel<<<32, 256>>>(g_Z_p, 2);
    gn_apply_kernel<<<NTOK * 256 / 256, 256>>>(gp_gamma, gp_beta, out);
}

// round 4
// speedup vs baseline: 1.4726x; 1.1729x over previous
#include <cuda_runtime.h>
#include <cuda_bf16.h>
#include <math.h>
#include <stdint.h>

#define BATCH 4
#define CCH 256
#define HWN 4096
#define NTOK 16384          // BATCH*HWN
#define CHW (CCH*HWN)
#define TOTAL (BATCH*CHW)
#define EPS_GN 1e-5f
#define LDT 40              // padded smem row length (bf16) for 32-wide K tile
#define NPART 16

// ---------------- scratch (device globals) ------------------------------------
__device__ float g_Y[(size_t)768 * NTOK];          // [768][16384] q|k|v channel-major
__device__ float g_attn[(size_t)CCH * NTOK];       // [256][16384] channel-major
__device__ float g_pos1[TOTAL];                    // NCHW
__device__ float g_U[(size_t)CCH * NTOK];          // [256][16384] channel-major
__device__ float g_Z[(size_t)CCH * NTOK];          // [256][16384] channel-major
__device__ float g_stats[3 * 32 * 2];              // [slot q/k/z][b*8+g][mean,rstd]
__device__ float g_part[3][32][NPART][2];          // partial sums
__device__ __nv_bfloat16 g_Whi[768 * 256], g_Wlo[768 * 256];
__device__ __nv_bfloat16 g_Wphi[256 * 256], g_Wplo[256 * 256];
__device__ __nv_bfloat16 g_Xhi[(size_t)NTOK * 256], g_Xlo[(size_t)NTOK * 256];
__device__ __nv_bfloat16 g_Uhi[(size_t)NTOK * 256], g_Ulo[(size_t)NTOK * 256];

// ---------------- helpers ------------------------------------------------------
__device__ __forceinline__ uint32_t smem_u32(const void* p) {
    return (uint32_t)__cvta_generic_to_shared(p);
}
__device__ __forceinline__ unsigned short f2bf_us(float v) {
    __nv_bfloat16 b = __float2bfloat16(v);
    return *reinterpret_cast<unsigned short*>(&b);
}
__device__ __forceinline__ void cp_async16(uint32_t s, const void* g) {
    asm volatile("cp.async.cg.shared.global [%0], [%1], 16;" :: "r"(s), "l"(g));
}
__device__ __forceinline__ void cp_commit() {
    asm volatile("cp.async.commit_group;");
}
__device__ __forceinline__ void ldsm_x4(uint32_t* r, uint32_t a) {
    asm volatile("ldmatrix.sync.aligned.m8n8.x4.shared.b16 {%0,%1,%2,%3}, [%4];"
                 : "=r"(r[0]), "=r"(r[1]), "=r"(r[2]), "=r"(r[3]) : "r"(a));
}
__device__ __forceinline__ void ldsm_x2(uint32_t* r, uint32_t a) {
    asm volatile("ldmatrix.sync.aligned.m8n8.x2.shared.b16 {%0,%1}, [%2];"
                 : "=r"(r[0]), "=r"(r[1]) : "r"(a));
}
__device__ __forceinline__ void mma_bf16(float* c, const uint32_t* a, const uint32_t* b) {
    asm volatile(
        "mma.sync.aligned.m16n8k16.row.col.f32.bf16.bf16.f32 "
        "{%0,%1,%2,%3}, {%4,%5,%6,%7}, {%8,%9}, {%0,%1,%2,%3};"
        : "+f"(c[0]), "+f"(c[1]), "+f"(c[2]), "+f"(c[3])
        : "r"(a[0]), "r"(a[1]), "r"(a[2]), "r"(a[3]), "r"(b[0]), "r"(b[1]));
}

// ---------------- W -> bf16 hi/lo (K-major already) ---------------------------
__global__ void convert_w_kernel(const float* __restrict__ wq, const float* __restrict__ wk,
                                 const float* __restrict__ wv, const float* __restrict__ wp) {
    int i = blockIdx.x * 256 + threadIdx.x;  // 0..262143
    float v;
    __nv_bfloat16 *hi, *lo;
    int o;
    if (i < 65536)        { v = wq[i];          o = i;          hi = g_Whi;  lo = g_Wlo; }
    else if (i < 131072)  { v = wk[i - 65536];  o = i;          hi = g_Whi;  lo = g_Wlo; }
    else if (i < 196608)  { v = wv[i - 131072]; o = i;          hi = g_Whi;  lo = g_Wlo; }
    else                  { v = wp[i - 196608]; o = i - 196608; hi = g_Wphi; lo = g_Wplo; }
    __nv_bfloat16 h = __float2bfloat16(v);
    hi[o] = h;
    lo[o] = __float2bfloat16(v - __bfloat162float(h));
}

// ---------------- transpose [c][hw] fp32 -> token-major bf16 hi/lo -------------
__global__ void transpose_convert_kernel(const float* __restrict__ src, int c_stride, int b_stride,
                                         __nv_bfloat16* __restrict__ dhi,
                                         __nv_bfloat16* __restrict__ dlo) {
    __shared__ float t[32][33];
    const int hw0 = blockIdx.x * 32, c0 = blockIdx.y * 32, b = blockIdx.z;
    const int tid = threadIdx.x;
    const int rl = tid >> 3, q = tid & 7;
    float4 v = *(const float4*)(src + (size_t)b * b_stride + (size_t)(c0 + rl) * c_stride + hw0 + q * 4);
    t[rl][q * 4 + 0] = v.x; t[rl][q * 4 + 1] = v.y;
    t[rl][q * 4 + 2] = v.z; t[rl][q * 4 + 3] = v.w;
    __syncthreads();
    const int n = b * HWN + hw0 + rl;
    ushort4 hs, ls;
    float f0 = t[q * 4 + 0][rl], f1 = t[q * 4 + 1][rl];
    float f2 = t[q * 4 + 2][rl], f3 = t[q * 4 + 3][rl];
    hs.x = f2bf_us(f0); hs.y = f2bf_us(f1); hs.z = f2bf_us(f2); hs.w = f2bf_us(f3);
    ls.x = f2bf_us(f0 - __bfloat162float(__float2bfloat16(f0)));
    ls.y = f2bf_us(f1 - __bfloat162float(__float2bfloat16(f1)));
    ls.z = f2bf_us(f2 - __bfloat162float(__float2bfloat16(f2)));
    ls.w = f2bf_us(f3 - __bfloat162float(__float2bfloat16(f3)));
    *(ushort4*)(dhi + (size_t)n * 256 + c0 + q * 4) = hs;
    *(ushort4*)(dlo + (size_t)n * 256 + c0 + q * 4) = ls;
}

// ---------------- mma.sync GEMM: out[m][n] = sum_k A[m][k]*B[n][k] -------------
// bf16 2-term split: Ahi*Bhi + Ahi*Blo + Alo*Bhi as K_eff = 3*256 = 768.
// 128x128 tile, BK=32, 8 warps (2x4), warp tile 64x32, cp.async double buffer.
__global__ __launch_bounds__(256) void mma_gemm_kernel(
    const __nv_bfloat16* __restrict__ Ahi, const __nv_bfloat16* __restrict__ Alo,
    const __nv_bfloat16* __restrict__ Bhi, const __nv_bfloat16* __restrict__ Blo,
    float* __restrict__ out, const float* __restrict__ bias) {
    __shared__ __nv_bfloat16 As[2][128 * LDT];
    __shared__ __nv_bfloat16 Bs[2][128 * LDT];
    const int tid = threadIdx.x;
    const int lane = tid & 31;
    const int wid = tid >> 5;
    const int wm = wid >> 2;          // 0..1
    const int wn = wid & 3;           // 0..3
    const int m0 = blockIdx.y * 128;
    const int n0 = blockIdx.x * 128;
    const int NITER = 24;             // 3 passes x 8

    float acc[4][4][4];
#pragma unroll
    for (int i = 0; i < 4; i++)
#pragma unroll
        for (int j = 0; j < 4; j++)
#pragma unroll
            for (int r = 0; r < 4; r++) acc[i][j][r] = 0.f;

    const int lrow = tid >> 1;            // 0..127
    const int lch2 = (tid & 1) * 2;       // chunk pairs {0,1} or {2,3}

#define LOAD_TILE(buf, kc)                                                              \
    do {                                                                                \
        int p = (kc) >> 3, k0 = ((kc) & 7) * 32;                                        \
        const __nv_bfloat16* ga = ((p == 2) ? Alo : Ahi) + (size_t)(m0 + lrow) * 256 + k0; \
        const __nv_bfloat16* gb = ((p == 1) ? Blo : Bhi) + (size_t)(n0 + lrow) * 256 + k0; \
        uint32_t sa = smem_u32(&As[buf][lrow * LDT + lch2 * 8]);                        \
        uint32_t sb = smem_u32(&Bs[buf][lrow * LDT + lch2 * 8]);                        \
        cp_async16(sa,      ga + lch2 * 8);                                             \
        cp_async16(sa + 16, ga + lch2 * 8 + 8);                                         \
        cp_async16(sb,      gb + lch2 * 8);                                             \
        cp_async16(sb + 16, gb + lch2 * 8 + 8);                                         \
        cp_commit();                                                                    \
    } while (0)

    LOAD_TILE(0, 0);

    int buf = 0;
    for (int kc = 0; kc < NITER; kc++) {
        if (kc + 1 < NITER) {
            LOAD_TILE(buf ^ 1, kc + 1);
            asm volatile("cp.async.wait_group 1;");
        } else {
            asm volatile("cp.async.wait_group 0;");
        }
        __syncthreads();

#pragma unroll
        for (int ks = 0; ks < 2; ks++) {
            uint32_t afr[4][4];
#pragma unroll
            for (int i = 0; i < 4; i++) {
                uint32_t a = smem_u32(&As[buf][(wm * 64 + i * 16 + (lane & 15)) * LDT +
                                              ((lane >> 4) * 8 + ks * 16)]);
                ldsm_x4(afr[i], a);
            }
            uint32_t bfr[4][2];
#pragma unroll
            for (int j = 0; j < 4; j++) {
                int l2 = lane & 15;
                uint32_t a = smem_u32(&Bs[buf][(wn * 32 + j * 8 + (l2 & 7)) * LDT +
                                              (((l2 >> 3) & 1) * 8 + ks * 16)]);
                ldsm_x2(bfr[j], a);
            }
#pragma unroll
            for (int i = 0; i < 4; i++)
#pragma unroll
                for (int j = 0; j < 4; j++) mma_bf16(acc[i][j], afr[i], bfr[j]);
        }
        __syncthreads();
        buf ^= 1;
    }
#undef LOAD_TILE

    // epilogue: direct float2 stores, channel-major out [m][NTOK]
#pragma unroll
    for (int i = 0; i < 4; i++) {
        const int row = m0 + wm * 64 + i * 16 + (lane >> 2);
        const float b0v = bias ? bias[row] : 0.f;
        const float b1v = bias ? bias[row + 8] : 0.f;
#pragma unroll
        for (int j = 0; j < 4; j++) {
            const int col = n0 + wn * 32 + j * 8 + (lane & 3) * 2;
            float2 v0 = make_float2(acc[i][j][0] + b0v, acc[i][j][1] + b0v);
            float2 v1 = make_float2(acc[i][j][2] + b1v, acc[i][j][3] + b1v);
            *(float2*)(out + (size_t)row * NTOK + col) = v0;
            *(float2*)(out + (size_t)(row + 8) * NTOK + col) = v1;
        }
    }
}

// ---------------- GN stats stage 1: partial sums (512 blocks/launch) -----------
// blockIdx.y = pair (b*8+g), blockIdx.x = part 0..NPART-1.
// Block reduces rows [g*32, g*32+32) x cols [b*4096 + part*256, +256).
__global__ __launch_bounds__(256) void gn_stats_part_kernel(const float* __restrict__ base, int slot) {
    const int pair = blockIdx.y;
    const int part = blockIdx.x;
    const int b = pair >> 3;
    const int g = pair & 7;
    const float* p = base + (size_t)(g * 32) * NTOK + b * HWN + part * 256;
    const int tid = threadIdx.x;
    const int c4 = tid & 63;          // float4 col within 256-chunk
    const int r0 = tid >> 6;          // 0..3
    float s = 0.f, s2 = 0.f;
#pragma unroll
    for (int it = 0; it < 8; it++) {
        int r = r0 + it * 4;
        float4 v = *(const float4*)(p + (size_t)r * NTOK + c4 * 4);
        s += v.x + v.y + v.z + v.w;
        s2 += v.x * v.x + v.y * v.y + v.z * v.z + v.w * v.w;
    }
    __shared__ float red[512];
    red[tid] = s; red[256 + tid] = s2;
    __syncthreads();
    for (int st = 128; st > 0; st >>= 1) {
        if (tid < st) {
            red[tid] += red[tid + st];
            red[256 + tid] += red[256 + tid + st];
        }
        __syncthreads();
    }
    if (tid == 0) {
        g_part[slot][pair][part][0] = red[0];
        g_part[slot][pair][part][1] = red[256];
    }
}

// ---------------- GN stats stage 2: finalize ----------------------------------
// grid.x = number of slots, finalizes slot = first + blockIdx.x; 32 threads.
__global__ void gn_finalize_kernel(int first) {
    const int slot = first + blockIdx.x;
    const int pair = threadIdx.x;  // 0..31
    float s = 0.f, s2 = 0.f;
#pragma unroll
    for (int p = 0; p < NPART; p++) {
        s += g_part[slot][pair][p][0];
        s2 += g_part[slot][pair][p][1];
    }
    const float inv = 1.f / 131072.f;
    float mean = s * inv;
    float var = s2 * inv - mean * mean;
    g_stats[(slot * 32 + pair) * 2 + 0] = mean;
    g_stats[(slot * 32 + pair) * 2 + 1] = rsqrtf(var + EPS_GN);
}

// ---------------- attention: 32 tokens/block, warp-per-token, smem k/v ---------
__global__ __launch_bounds__(1024) void attn_kernel(
    const float* __restrict__ gqg, const float* __restrict__ gqb,
    const float* __restrict__ gkg, const float* __restrict__ gkb) {
    extern __shared__ float smf[];
    float* smq = smf;                 // [256][33]
    float* smk = smf + 256 * 33;
    float* smv = smf + 2 * 256 * 33;
    float* knb = smf + 3 * 256 * 33;  // [32 warps][32]
    const int tid = threadIdx.x;
    const int warp = tid >> 5;
    const int lane = tid & 31;
    const int n0 = blockIdx.x * 32;
    const int b = n0 >> 12;

#pragma unroll
    for (int r = 0; r < 6; r++) {
        const int tens = r >> 1;
        const int slot = tid + r * 1024;
        const int row = (slot >> 3) & 255;
        const int q = slot & 7;
        float4 v = *(const float4*)(g_Y + (size_t)(tens * 256 + row) * NTOK + n0 + q * 4);
        float* dst = smf + tens * (256 * 33) + row * 33 + q * 4;
        dst[0] = v.x; dst[1] = v.y; dst[2] = v.z; dst[3] = v.w;
    }
    __syncthreads();

    const float scale_l2e = 0.17677669529663687f * 1.4426950408889634f;
    float oacc[8];
#pragma unroll 1
    for (int h = 0; h < 8; h++) {
        const int c = h * 32 + lane;
        float q = smq[c * 33 + warp];
        float k = smk[c * 33 + warp];
        const int qi = (b * 8 + h) * 2;
        const int ki = (32 + b * 8 + h) * 2;
        q = (q - g_stats[qi]) * g_stats[qi + 1] * gqg[c] + gqb[c];
        k = (k - g_stats[ki]) * g_stats[ki + 1] * gkg[c] + gkb[c];
        float sq = q * q, sk = k * k;
#pragma unroll
        for (int off = 16; off > 0; off >>= 1) {
            sq += __shfl_xor_sync(0xffffffffu, sq, off);
            sk += __shfl_xor_sync(0xffffffffu, sk, off);
        }
        const float qn = q / fmaxf(sqrtf(sq), 1e-12f);
        const float kn = k / fmaxf(sqrtf(sk), 1e-12f);
        __syncwarp();
        knb[warp * 32 + lane] = kn;
        __syncwarp();
        const float s2 = qn * scale_l2e;
        float num = 0.f, den = 0.f;
#pragma unroll
        for (int e = 0; e < 32; e++) {
            float ke = knb[warp * 32 + e];
            float ve = smv[(h * 32 + e) * 33 + warp];
            float t = s2 * ke;
            float w;
            asm("ex2.approx.f32 %0, %1;" : "=f"(w) : "f"(t));
            den += w;
            num = fmaf(w, ve, num);
        }
        oacc[h] = num / den;
    }
#pragma unroll
    for (int h = 0; h < 8; h++) smq[(h * 32 + lane) * 33 + warp] = oacc[h];
    __syncthreads();
#pragma unroll
    for (int it = 0; it < 8; it++) {
        int idx = tid + it * 1024;
        int c = idx >> 5, j = idx & 31;
        g_attn[(size_t)c * NTOK + n0 + j] = smq[c * 33 + j];
    }
}

// ---------------- depthwise conv 3x3 + GeLU (exact) ----------------------------
__global__ void dwconv1_gelu_kernel(const float* __restrict__ x,
                                    const float* __restrict__ dw,
                                    const float* __restrict__ db) {
    int idx = blockIdx.x * 256 + threadIdx.x;
    if (idx >= TOTAL) return;
    const int px = idx & 63;
    const int py = (idx >> 6) & 63;
    const int c = (idx >> 12) & 255;
    const float* xb = x + (size_t)(idx >> 12) * HWN;
    const float* wc = dw + c * 9;
    float acc = db[c];
#pragma unroll
    for (int dy = -1; dy <= 1; dy++) {
        int yy = py + dy;
        if ((unsigned)yy > 63u) continue;
#pragma unroll
        for (int dx = -1; dx <= 1; dx++) {
            int xx = px + dx;
            if ((unsigned)xx > 63u) continue;
            acc = fmaf(xb[yy * 64 + xx], wc[(dy + 1) * 3 + (dx + 1)], acc);
        }
    }
    g_pos1[idx] = 0.5f * acc * (1.f + erff(acc * 0.70710678118654752f));
}

// pos2 = dwconv3x3(pos1) + db2; U = pos2 + attn (U channel-major [c][n])
__global__ void dwconv2_add_kernel(const float* __restrict__ dw,
                                   const float* __restrict__ db) {
    int idx = blockIdx.x * 256 + threadIdx.x;
    if (idx >= TOTAL) return;
    const int px = idx & 63;
    const int py = (idx >> 6) & 63;
    const int c = (idx >> 12) & 255;
    const int b = idx >> 20;
    const float* xb = g_pos1 + (size_t)(idx >> 12) * HWN;
    const float* wc = dw + c * 9;
    float acc = db[c];
#pragma unroll
    for (int dy = -1; dy <= 1; dy++) {
        int yy = py + dy;
        if ((unsigned)yy > 63u) continue;
#pragma unroll
        for (int dx = -1; dx <= 1; dx++) {
            int xx = px + dx;
            if ((unsigned)xx > 63u) continue;
            acc = fmaf(xb[yy * 64 + xx], wc[(dy + 1) * 3 + (dx + 1)], acc);
        }
    }
    const size_t cn = (size_t)c * NTOK + b * HWN + (idx & 4095);
    g_U[cn] = acc + g_attn[cn];
}

// ---------------- final GN apply (channel-major in, NCHW out) ------------------
__global__ void gn_apply_kernel(const float* __restrict__ gamma,
                                const float* __restrict__ beta,
                                float* __restrict__ out) {
    int idx = blockIdx.x * 256 + threadIdx.x;  // over 256*16384
    const int c = idx >> 14;
    const int n = idx & 16383;
    const int b = n >> 12;
    const int g = c >> 5;
    const int si = (2 * 32 + b * 8 + g) * 2;
    float v = (g_Z[idx] - g_stats[si]) * g_stats[si + 1] * gamma[c] + beta[c];
    out[(size_t)b * CHW + (size_t)c * HWN + (n & 4095)] = v;
}

// ---------------- launcher -----------------------------------------------------
extern "C" void kernel_launch(void* const* d_in, const int* in_sizes, int n_in,
                              void* d_out, int out_size) {
    const float* x        = (const float*)d_in[0];
    const float* wq       = (const float*)d_in[1];
    const float* gq_gamma = (const float*)d_in[2];
    const float* gq_beta  = (const float*)d_in[3];
    const float* wk       = (const float*)d_in[4];
    const float* gk_gamma = (const float*)d_in[5];
    const float* gk_beta  = (const float*)d_in[6];
    const float* wv       = (const float*)d_in[7];
    const float* wp       = (const float*)d_in[8];
    const float* bp       = (const float*)d_in[9];
    const float* gp_gamma = (const float*)d_in[10];
    const float* gp_beta  = (const float*)d_in[11];
    const float* dw1      = (const float*)d_in[12];
    const float* db1      = (const float*)d_in[13];
    const float* dw2      = (const float*)d_in[14];
    const float* db2      = (const float*)d_in[15];
    float* out = (float*)d_out;

    static bool attr_set = false;
    if (!attr_set) {
        cudaFuncSetAttribute(attn_kernel, cudaFuncAttributeMaxDynamicSharedMemorySize, 105472);
        attr_set = true;
    }

    float *g_Y_p, *g_U_p, *g_Z_p;
    __nv_bfloat16 *whi, *wlo, *wphi, *wplo, *xhi, *xlo, *uhi, *ulo;
    cudaGetSymbolAddress((void**)&g_Y_p, g_Y);
    cudaGetSymbolAddress((void**)&g_U_p, g_U);
    cudaGetSymbolAddress((void**)&g_Z_p, g_Z);
    cudaGetSymbolAddress((void**)&whi, g_Whi);
    cudaGetSymbolAddress((void**)&wlo, g_Wlo);
    cudaGetSymbolAddress((void**)&wphi, g_Wphi);
    cudaGetSymbolAddress((void**)&wplo, g_Wplo);
    cudaGetSymbolAddress((void**)&xhi, g_Xhi);
    cudaGetSymbolAddress((void**)&xlo, g_Xlo);
    cudaGetSymbolAddress((void**)&uhi, g_Uhi);
    cudaGetSymbolAddress((void**)&ulo, g_Ulo);

    // 1. weight + input conversion
    convert_w_kernel<<<1024, 256>>>(wq, wk, wv, wp);
    transpose_convert_kernel<<<dim3(128, 8, BATCH), 256>>>(x, HWN, CHW, xhi, xlo);
    // 2. QKV GEMM (mma.sync bf16 split) -> g_Y [768][16384]
    mma_gemm_kernel<<<dim3(128, 6), 256>>>(whi, wlo, xhi, xlo, g_Y_p, nullptr);
    // 3. GN stats for q, k (two-stage, 512 blocks each)
    gn_stats_part_kernel<<<dim3(NPART, 32), 256>>>(g_Y_p, 0);
    gn_stats_part_kernel<<<dim3(NPART, 32), 256>>>(g_Y_p + (size_t)256 * NTOK, 1);
    gn_finalize_kernel<<<2, 32>>>(0);
    // 4. attention -> g_attn [c][n]
    attn_kernel<<<512, 1024, 105472>>>(gq_gamma, gq_beta, gk_gamma, gk_beta);
    // 5. positional path
    dwconv1_gelu_kernel<<<TOTAL / 256, 256>>>(x, dw1, db1);
    dwconv2_add_kernel<<<TOTAL / 256, 256>>>(dw2, db2);
    // 6. U -> token-major bf16, output projection GEMM -> g_Z [256][16384]
    transpose_convert_kernel<<<dim3(128, 8, BATCH), 256>>>(g_U_p, NTOK, HWN, uhi, ulo);
    mma_gemm_kernel<<<dim3(128, 2), 256>>>(wphi, wplo, uhi, ulo, g_Z_p, bp);
    // 7. final group norm (two-stage)
    gn_stats_part_kernel<<<dim3(NPART, 32), 256>>>(g_Z_p, 2);
    gn_finalize_kernel<<<1, 32>>>(2);
    gn_apply_kernel<<<NTOK * 256 / 256, 256>>>(gp_gamma, gp_beta, out);
}

// round 5
// speedup vs baseline: 1.6243x; 1.1030x over previous
#include <cuda_runtime.h>
#include <cuda_bf16.h>
#include <math.h>
#include <stdint.h>

#define BATCH 4
#define CCH 256
#define HWN 4096
#define NTOK 16384          // BATCH*HWN
#define CHW (CCH*HWN)
#define TOTAL (BATCH*CHW)
#define EPS_GN 1e-5f
#define LDT 40              // padded smem row length (bf16) for 32-wide K tile
#define NPART 16

// ---------------- scratch (device globals) ------------------------------------
__device__ float g_Y[(size_t)768 * NTOK];          // [768][16384] q|k|v channel-major
__device__ float g_pos[TOTAL];                     // NCHW positional branch output
__device__ float g_Z[(size_t)CCH * NTOK];          // [256][16384] channel-major
__device__ float g_stats[3 * 32 * 2];              // [slot q/k/z][b*8+g][mean,rstd]
__device__ float g_part[3][32][NPART][2];          // partial sums
__device__ __nv_bfloat16 g_Whi[768 * 256], g_Wlo[768 * 256];
__device__ __nv_bfloat16 g_Wphi[256 * 256], g_Wplo[256 * 256];
__device__ __nv_bfloat16 g_Xhi[(size_t)NTOK * 256], g_Xlo[(size_t)NTOK * 256];
__device__ __nv_bfloat16 g_Uhi[(size_t)NTOK * 256], g_Ulo[(size_t)NTOK * 256];

// ---------------- helpers ------------------------------------------------------
__device__ __forceinline__ uint32_t smem_u32(const void* p) {
    return (uint32_t)__cvta_generic_to_shared(p);
}
__device__ __forceinline__ unsigned short f2bf_us(float v) {
    __nv_bfloat16 b = __float2bfloat16(v);
    return *reinterpret_cast<unsigned short*>(&b);
}
__device__ __forceinline__ void cp_async16(uint32_t s, const void* g) {
    asm volatile("cp.async.cg.shared.global [%0], [%1], 16;" :: "r"(s), "l"(g));
}
__device__ __forceinline__ void cp_commit() {
    asm volatile("cp.async.commit_group;");
}
__device__ __forceinline__ void ldsm_x4(uint32_t* r, uint32_t a) {
    asm volatile("ldmatrix.sync.aligned.m8n8.x4.shared.b16 {%0,%1,%2,%3}, [%4];"
                 : "=r"(r[0]), "=r"(r[1]), "=r"(r[2]), "=r"(r[3]) : "r"(a));
}
__device__ __forceinline__ void ldsm_x2(uint32_t* r, uint32_t a) {
    asm volatile("ldmatrix.sync.aligned.m8n8.x2.shared.b16 {%0,%1}, [%2];"
                 : "=r"(r[0]), "=r"(r[1]) : "r"(a));
}
__device__ __forceinline__ void mma_bf16(float* c, const uint32_t* a, const uint32_t* b) {
    asm volatile(
        "mma.sync.aligned.m16n8k16.row.col.f32.bf16.bf16.f32 "
        "{%0,%1,%2,%3}, {%4,%5,%6,%7}, {%8,%9}, {%0,%1,%2,%3};"
        : "+f"(c[0]), "+f"(c[1]), "+f"(c[2]), "+f"(c[3])
        : "r"(a[0]), "r"(a[1]), "r"(a[2]), "r"(a[3]), "r"(b[0]), "r"(b[1]));
}

// ---------------- W -> bf16 hi/lo (K-major already) ---------------------------
__global__ void convert_w_kernel(const float* __restrict__ wq, const float* __restrict__ wk,
                                 const float* __restrict__ wv, const float* __restrict__ wp) {
    int i = blockIdx.x * 256 + threadIdx.x;  // 0..262143
    float v;
    __nv_bfloat16 *hi, *lo;
    int o;
    if (i < 65536)        { v = wq[i];          o = i;          hi = g_Whi;  lo = g_Wlo; }
    else if (i < 131072)  { v = wk[i - 65536];  o = i;          hi = g_Whi;  lo = g_Wlo; }
    else if (i < 196608)  { v = wv[i - 131072]; o = i;          hi = g_Whi;  lo = g_Wlo; }
    else                  { v = wp[i - 196608]; o = i - 196608; hi = g_Wphi; lo = g_Wplo; }
    __nv_bfloat16 h = __float2bfloat16(v);
    hi[o] = h;
    lo[o] = __float2bfloat16(v - __bfloat162float(h));
}

// ---------------- transpose [c][hw] fp32 -> token-major bf16 hi/lo -------------
__global__ void transpose_convert_kernel(const float* __restrict__ src, int c_stride, int b_stride,
                                         __nv_bfloat16* __restrict__ dhi,
                                         __nv_bfloat16* __restrict__ dlo) {
    __shared__ float t[32][33];
    const int hw0 = blockIdx.x * 32, c0 = blockIdx.y * 32, b = blockIdx.z;
    const int tid = threadIdx.x;
    const int rl = tid >> 3, q = tid & 7;
    float4 v = *(const float4*)(src + (size_t)b * b_stride + (size_t)(c0 + rl) * c_stride + hw0 + q * 4);
    t[rl][q * 4 + 0] = v.x; t[rl][q * 4 + 1] = v.y;
    t[rl][q * 4 + 2] = v.z; t[rl][q * 4 + 3] = v.w;
    __syncthreads();
    const int n = b * HWN + hw0 + rl;
    ushort4 hs, ls;
    float f0 = t[q * 4 + 0][rl], f1 = t[q * 4 + 1][rl];
    float f2 = t[q * 4 + 2][rl], f3 = t[q * 4 + 3][rl];
    hs.x = f2bf_us(f0); hs.y = f2bf_us(f1); hs.z = f2bf_us(f2); hs.w = f2bf_us(f3);
    ls.x = f2bf_us(f0 - __bfloat162float(__float2bfloat16(f0)));
    ls.y = f2bf_us(f1 - __bfloat162float(__float2bfloat16(f1)));
    ls.z = f2bf_us(f2 - __bfloat162float(__float2bfloat16(f2)));
    ls.w = f2bf_us(f3 - __bfloat162float(__float2bfloat16(f3)));
    *(ushort4*)(dhi + (size_t)n * 256 + c0 + q * 4) = hs;
    *(ushort4*)(dlo + (size_t)n * 256 + c0 + q * 4) = ls;
}

// ---------------- mma.sync GEMM: out[m][n] = sum_k A[m][k]*B[n][k] -------------
__global__ __launch_bounds__(256) void mma_gemm_kernel(
    const __nv_bfloat16* __restrict__ Ahi, const __nv_bfloat16* __restrict__ Alo,
    const __nv_bfloat16* __restrict__ Bhi, const __nv_bfloat16* __restrict__ Blo,
    float* __restrict__ out, const float* __restrict__ bias) {
    __shared__ __nv_bfloat16 As[2][128 * LDT];
    __shared__ __nv_bfloat16 Bs[2][128 * LDT];
    const int tid = threadIdx.x;
    const int lane = tid & 31;
    const int wid = tid >> 5;
    const int wm = wid >> 2;          // 0..1
    const int wn = wid & 3;           // 0..3
    const int m0 = blockIdx.y * 128;
    const int n0 = blockIdx.x * 128;
    const int NITER = 24;             // 3 passes x 8

    float acc[4][4][4];
#pragma unroll
    for (int i = 0; i < 4; i++)
#pragma unroll
        for (int j = 0; j < 4; j++)
#pragma unroll
            for (int r = 0; r < 4; r++) acc[i][j][r] = 0.f;

    const int lrow = tid >> 1;            // 0..127
    const int lch2 = (tid & 1) * 2;       // chunk pairs {0,1} or {2,3}

#define LOAD_TILE(buf, kc)                                                              \
    do {                                                                                \
        int p = (kc) >> 3, k0 = ((kc) & 7) * 32;                                        \
        const __nv_bfloat16* ga = ((p == 2) ? Alo : Ahi) + (size_t)(m0 + lrow) * 256 + k0; \
        const __nv_bfloat16* gb = ((p == 1) ? Blo : Bhi) + (size_t)(n0 + lrow) * 256 + k0; \
        uint32_t sa = smem_u32(&As[buf][lrow * LDT + lch2 * 8]);                        \
        uint32_t sb = smem_u32(&Bs[buf][lrow * LDT + lch2 * 8]);                        \
        cp_async16(sa,      ga + lch2 * 8);                                             \
        cp_async16(sa + 16, ga + lch2 * 8 + 8);                                         \
        cp_async16(sb,      gb + lch2 * 8);                                             \
        cp_async16(sb + 16, gb + lch2 * 8 + 8);                                         \
        cp_commit();                                                                    \
    } while (0)

    LOAD_TILE(0, 0);

    int buf = 0;
    for (int kc = 0; kc < NITER; kc++) {
        if (kc + 1 < NITER) {
            LOAD_TILE(buf ^ 1, kc + 1);
            asm volatile("cp.async.wait_group 1;");
        } else {
            asm volatile("cp.async.wait_group 0;");
        }
        __syncthreads();

#pragma unroll
        for (int ks = 0; ks < 2; ks++) {
            uint32_t afr[4][4];
#pragma unroll
            for (int i = 0; i < 4; i++) {
                uint32_t a = smem_u32(&As[buf][(wm * 64 + i * 16 + (lane & 15)) * LDT +
                                              ((lane >> 4) * 8 + ks * 16)]);
                ldsm_x4(afr[i], a);
            }
            uint32_t bfr[4][2];
#pragma unroll
            for (int j = 0; j < 4; j++) {
                int l2 = lane & 15;
                uint32_t a = smem_u32(&Bs[buf][(wn * 32 + j * 8 + (l2 & 7)) * LDT +
                                              (((l2 >> 3) & 1) * 8 + ks * 16)]);
                ldsm_x2(bfr[j], a);
            }
#pragma unroll
            for (int i = 0; i < 4; i++)
#pragma unroll
                for (int j = 0; j < 4; j++) mma_bf16(acc[i][j], afr[i], bfr[j]);
        }
        __syncthreads();
        buf ^= 1;
    }
#undef LOAD_TILE

#pragma unroll
    for (int i = 0; i < 4; i++) {
        const int row = m0 + wm * 64 + i * 16 + (lane >> 2);
        const float b0v = bias ? bias[row] : 0.f;
        const float b1v = bias ? bias[row + 8] : 0.f;
#pragma unroll
        for (int j = 0; j < 4; j++) {
            const int col = n0 + wn * 32 + j * 8 + (lane & 3) * 2;
            float2 v0 = make_float2(acc[i][j][0] + b0v, acc[i][j][1] + b0v);
            float2 v1 = make_float2(acc[i][j][2] + b1v, acc[i][j][3] + b1v);
            *(float2*)(out + (size_t)row * NTOK + col) = v0;
            *(float2*)(out + (size_t)(row + 8) * NTOK + col) = v1;
        }
    }
}

// ---------------- GN stats stage 1: partial sums -------------------------------
__global__ __launch_bounds__(256) void gn_stats_part_kernel(const float* __restrict__ base, int slot) {
    const int pair = blockIdx.y;
    const int part = blockIdx.x;
    const int b = pair >> 3;
    const int g = pair & 7;
    const float* p = base + (size_t)(g * 32) * NTOK + b * HWN + part * 256;
    const int tid = threadIdx.x;
    const int c4 = tid & 63;
    const int r0 = tid >> 6;
    float s = 0.f, s2 = 0.f;
#pragma unroll
    for (int it = 0; it < 8; it++) {
        int r = r0 + it * 4;
        float4 v = *(const float4*)(p + (size_t)r * NTOK + c4 * 4);
        s += v.x + v.y + v.z + v.w;
        s2 += v.x * v.x + v.y * v.y + v.z * v.z + v.w * v.w;
    }
    __shared__ float red[512];
    red[tid] = s; red[256 + tid] = s2;
    __syncthreads();
    for (int st = 128; st > 0; st >>= 1) {
        if (tid < st) {
            red[tid] += red[tid + st];
            red[256 + tid] += red[256 + tid + st];
        }
        __syncthreads();
    }
    if (tid == 0) {
        g_part[slot][pair][part][0] = red[0];
        g_part[slot][pair][part][1] = red[256];
    }
}

// ---------------- GN stats stage 2: finalize ----------------------------------
__global__ void gn_finalize_kernel(int first) {
    const int slot = first + blockIdx.x;
    const int pair = threadIdx.x;  // 0..31
    float s = 0.f, s2 = 0.f;
#pragma unroll
    for (int p = 0; p < NPART; p++) {
        s += g_part[slot][pair][p][0];
        s2 += g_part[slot][pair][p][1];
    }
    const float inv = 1.f / 131072.f;
    float mean = s * inv;
    float var = s2 * inv - mean * mean;
    g_stats[(slot * 32 + pair) * 2 + 0] = mean;
    g_stats[(slot * 32 + pair) * 2 + 1] = rsqrtf(var + EPS_GN);
}

// ---------------- fused depthwise conv 3x3 + GeLU + conv 3x3 -------------------
// One block per (b,c): full 64x64 plane through smem; pos1 never hits DRAM.
__global__ __launch_bounds__(256) void dwconv_fused_kernel(
    const float* __restrict__ x,
    const float* __restrict__ dw1, const float* __restrict__ db1,
    const float* __restrict__ dw2, const float* __restrict__ db2) {
    __shared__ float xs[64 * 64];
    __shared__ float p1[64 * 65];
    const int bc = blockIdx.x;          // b*256 + c
    const int c = bc & 255;
    const float* xb = x + (size_t)bc * HWN;
    const int tid = threadIdx.x;

#pragma unroll
    for (int i = 0; i < 4; i++) {
        int idx = tid + i * 256;        // float4 slots (1024 total)
        *(float4*)&xs[idx * 4] = *(const float4*)(xb + idx * 4);
    }
    float w1[9], w2[9];
#pragma unroll
    for (int i = 0; i < 9; i++) { w1[i] = dw1[c * 9 + i]; w2[i] = dw2[c * 9 + i]; }
    const float b1 = db1[c], b2 = db2[c];
    __syncthreads();

#pragma unroll
    for (int i = 0; i < 16; i++) {
        int idx = tid + i * 256;
        int px = idx & 63, py = idx >> 6;
        float acc = b1;
#pragma unroll
        for (int dy = -1; dy <= 1; dy++) {
            int yy = py + dy;
            if ((unsigned)yy > 63u) continue;
#pragma unroll
            for (int dx = -1; dx <= 1; dx++) {
                int xx = px + dx;
                if ((unsigned)xx > 63u) continue;
                acc = fmaf(xs[yy * 64 + xx], w1[(dy + 1) * 3 + (dx + 1)], acc);
            }
        }
        p1[py * 65 + px] = 0.5f * acc * (1.f + erff(acc * 0.70710678118654752f));
    }
    __syncthreads();

#pragma unroll
    for (int i = 0; i < 16; i++) {
        int idx = tid + i * 256;
        int px = idx & 63, py = idx >> 6;
        float acc = b2;
#pragma unroll
        for (int dy = -1; dy <= 1; dy++) {
            int yy = py + dy;
            if ((unsigned)yy > 63u) continue;
#pragma unroll
            for (int dx = -1; dx <= 1; dx++) {
                int xx = px + dx;
                if ((unsigned)xx > 63u) continue;
                acc = fmaf(p1[yy * 65 + xx], w2[(dy + 1) * 3 + (dx + 1)], acc);
            }
        }
        g_pos[(size_t)bc * HWN + idx] = acc;
    }
}

// ---------------- attention + residual + bf16 split emission -------------------
// 32 tokens/block, warp-per-token. Emits U = attn_out + pos directly as
// token-major bf16 hi/lo (GEMM2 operand layout). No fp32 U / attn arrays.
__global__ __launch_bounds__(1024) void attn_kernel(
    const float* __restrict__ gqg, const float* __restrict__ gqb,
    const float* __restrict__ gkg, const float* __restrict__ gkb) {
    extern __shared__ float smf[];
    float* smq = smf;                 // [256][33]
    float* smk = smf + 256 * 33;
    float* smv = smf + 2 * 256 * 33;
    float* smp = smf + 3 * 256 * 33;  // pos tile
    float* kv  = smf + 4 * 256 * 33;  // [32 warps][64]: interleaved (k,v)
    const int tid = threadIdx.x;
    const int warp = tid >> 5;
    const int lane = tid & 31;
    const int n0 = blockIdx.x * 32;
    const int b = n0 >> 12;
    const int hw0 = n0 & 4095;

#pragma unroll
    for (int r = 0; r < 6; r++) {
        const int tens = r >> 1;
        const int slot = tid + r * 1024;
        const int row = (slot >> 3) & 255;
        const int q8 = slot & 7;
        float4 v = *(const float4*)(g_Y + (size_t)(tens * 256 + row) * NTOK + n0 + q8 * 4);
        float* dst = smf + tens * (256 * 33) + row * 33 + q8 * 4;
        dst[0] = v.x; dst[1] = v.y; dst[2] = v.z; dst[3] = v.w;
    }
#pragma unroll
    for (int r = 0; r < 2; r++) {
        const int slot = tid + r * 1024;
        const int row = (slot >> 3) & 255;
        const int q8 = slot & 7;
        float4 v = *(const float4*)(g_pos + (size_t)b * CHW + (size_t)row * HWN + hw0 + q8 * 4);
        float* dst = smp + row * 33 + q8 * 4;
        dst[0] = v.x; dst[1] = v.y; dst[2] = v.z; dst[3] = v.w;
    }
    __syncthreads();

    const float scale_l2e = 0.17677669529663687f * 1.4426950408889634f;
    float oacc[8];
#pragma unroll 1
    for (int h = 0; h < 8; h++) {
        const int c = h * 32 + lane;
        float q = smq[c * 33 + warp];
        float k = smk[c * 33 + warp];
        float vv = smv[c * 33 + warp];
        const int qi = (b * 8 + h) * 2;
        const int ki = (32 + b * 8 + h) * 2;
        q = (q - g_stats[qi]) * g_stats[qi + 1] * gqg[c] + gqb[c];
        k = (k - g_stats[ki]) * g_stats[ki + 1] * gkg[c] + gkb[c];
        float sq = q * q, sk = k * k;
#pragma unroll
        for (int off = 16; off > 0; off >>= 1) {
            sq += __shfl_xor_sync(0xffffffffu, sq, off);
            sk += __shfl_xor_sync(0xffffffffu, sk, off);
        }
        const float qn = q / fmaxf(sqrtf(sq), 1e-12f);
        const float kn = k / fmaxf(sqrtf(sk), 1e-12f);
        __syncwarp();
        *(float2*)&kv[warp * 64 + lane * 2] = make_float2(kn, vv);
        __syncwarp();
        const float s2 = qn * scale_l2e;
        float num = 0.f, den = 0.f;
#pragma unroll
        for (int e = 0; e < 32; e++) {
            float2 kvp = *(const float2*)&kv[warp * 64 + e * 2];
            float t = s2 * kvp.x;
            float w;
            asm("ex2.approx.f32 %0, %1;" : "=f"(w) : "f"(t));
            den += w;
            num = fmaf(w, kvp.y, num);
        }
        oacc[h] = num / den + smp[c * 33 + warp];
    }
#pragma unroll
    for (int h = 0; h < 8; h++) smq[(h * 32 + lane) * 33 + warp] = oacc[h];
    __syncthreads();

    // emit token-major bf16 hi/lo: U[n][256]
#pragma unroll
    for (int it = 0; it < 2; it++) {
        const int j = (tid >> 6) + it * 16;   // token 0..31
        const int c0 = (tid & 63) * 4;
        float f0 = smq[(c0 + 0) * 33 + j];
        float f1 = smq[(c0 + 1) * 33 + j];
        float f2 = smq[(c0 + 2) * 33 + j];
        float f3 = smq[(c0 + 3) * 33 + j];
        ushort4 hs, ls;
        hs.x = f2bf_us(f0); hs.y = f2bf_us(f1); hs.z = f2bf_us(f2); hs.w = f2bf_us(f3);
        ls.x = f2bf_us(f0 - __bfloat162float(__float2bfloat16(f0)));
        ls.y = f2bf_us(f1 - __bfloat162float(__float2bfloat16(f1)));
        ls.z = f2bf_us(f2 - __bfloat162float(__float2bfloat16(f2)));
        ls.w = f2bf_us(f3 - __bfloat162float(__float2bfloat16(f3)));
        const size_t n = (size_t)(n0 + j);
        *(ushort4*)(g_Uhi + n * 256 + c0) = hs;
        *(ushort4*)(g_Ulo + n * 256 + c0) = ls;
    }
}

// ---------------- final GN apply (channel-major in, NCHW out) ------------------
__global__ void gn_apply_kernel(const float* __restrict__ gamma,
                                const float* __restrict__ beta,
                                float* __restrict__ out) {
    int idx = blockIdx.x * 256 + threadIdx.x;  // over 256*16384
    const int c = idx >> 14;
    const int n = idx & 16383;
    const int b = n >> 12;
    const int g = c >> 5;
    const int si = (2 * 32 + b * 8 + g) * 2;
    float v = (g_Z[idx] - g_stats[si]) * g_stats[si + 1] * gamma[c] + beta[c];
    out[(size_t)b * CHW + (size_t)c * HWN + (n & 4095)] = v;
}

// ---------------- launcher -----------------------------------------------------
extern "C" void kernel_launch(void* const* d_in, const int* in_sizes, int n_in,
                              void* d_out, int out_size) {
    const float* x        = (const float*)d_in[0];
    const float* wq       = (const float*)d_in[1];
    const float* gq_gamma = (const float*)d_in[2];
    const float* gq_beta  = (const float*)d_in[3];
    const float* wk       = (const float*)d_in[4];
    const float* gk_gamma = (const float*)d_in[5];
    const float* gk_beta  = (const float*)d_in[6];
    const float* wv       = (const float*)d_in[7];
    const float* wp       = (const float*)d_in[8];
    const float* bp       = (const float*)d_in[9];
    const float* gp_gamma = (const float*)d_in[10];
    const float* gp_beta  = (const float*)d_in[11];
    const float* dw1      = (const float*)d_in[12];
    const float* db1      = (const float*)d_in[13];
    const float* dw2      = (const float*)d_in[14];
    const float* db2      = (const float*)d_in[15];
    float* out = (float*)d_out;

    static bool attr_set = false;
    if (!attr_set) {
        cudaFuncSetAttribute(attn_kernel, cudaFuncAttributeMaxDynamicSharedMemorySize, 143360);
        attr_set = true;
    }

    float *g_Y_p, *g_Z_p;
    __nv_bfloat16 *whi, *wlo, *wphi, *wplo, *xhi, *xlo, *uhi, *ulo;
    cudaGetSymbolAddress((void**)&g_Y_p, g_Y);
    cudaGetSymbolAddress((void**)&g_Z_p, g_Z);
    cudaGetSymbolAddress((void**)&whi, g_Whi);
    cudaGetSymbolAddress((void**)&wlo, g_Wlo);
    cudaGetSymbolAddress((void**)&wphi, g_Wphi);
    cudaGetSymbolAddress((void**)&wplo, g_Wplo);
    cudaGetSymbolAddress((void**)&xhi, g_Xhi);
    cudaGetSymbolAddress((void**)&xlo, g_Xlo);
    cudaGetSymbolAddress((void**)&uhi, g_Uhi);
    cudaGetSymbolAddress((void**)&ulo, g_Ulo);

    // 1. weight + input conversion
    convert_w_kernel<<<1024, 256>>>(wq, wk, wv, wp);
    transpose_convert_kernel<<<dim3(128, 8, BATCH), 256>>>(x, HWN, CHW, xhi, xlo);
    // 2. QKV GEMM -> g_Y [768][16384]
    mma_gemm_kernel<<<dim3(128, 6), 256>>>(whi, wlo, xhi, xlo, g_Y_p, nullptr);
    // 3. GN stats for q, k
    gn_stats_part_kernel<<<dim3(NPART, 32), 256>>>(g_Y_p, 0);
    gn_stats_part_kernel<<<dim3(NPART, 32), 256>>>(g_Y_p + (size_t)256 * NTOK, 1);
    gn_finalize_kernel<<<2, 32>>>(0);
    // 4. fused positional path -> g_pos
    dwconv_fused_kernel<<<1024, 256>>>(x, dw1, db1, dw2, db2);
    // 5. attention + residual -> U bf16 hi/lo (token-major) directly
    attn_kernel<<<512, 1024, 143360>>>(gq_gamma, gq_beta, gk_gamma, gk_beta);
    // 6. output projection GEMM -> g_Z [256][16384]
    mma_gemm_kernel<<<dim3(128, 2), 256>>>(wphi, wplo, uhi, ulo, g_Z_p, bp);
    // 7. final group norm
    gn_stats_part_kernel<<<dim3(NPART, 32), 256>>>(g_Z_p, 2);
    gn_finalize_kernel<<<1, 32>>>(2);
    gn_apply_kernel<<<NTOK * 256 / 256, 256>>>(gp_gamma, gp_beta, out);
}

// round 6
// speedup vs baseline: 1.6963x; 1.0444x over previous
#include <cuda_runtime.h>
#include <cuda_bf16.h>
#include <math.h>
#include <stdint.h>

#define BATCH 4
#define CCH 256
#define HWN 4096
#define NTOK 16384          // BATCH*HWN
#define CHW (CCH*HWN)
#define TOTAL (BATCH*CHW)
#define EPS_GN 1e-5f
#define LDT 40              // padded smem row length (bf16) for 32-wide K tile
#define NPART 32            // n-tiles per batch (4096/128)

// ---------------- scratch (device globals) ------------------------------------
__device__ float g_Y[(size_t)768 * NTOK];          // [768][16384] q|k|v channel-major
__device__ float g_pos[TOTAL];                     // NCHW positional branch output
__device__ float g_Z[(size_t)CCH * NTOK];          // [256][16384] channel-major
__device__ float g_stats[3 * 32 * 2];              // [slot q/k/z][b*8+g][mean,rstd]
__device__ float g_part[3][32][NPART][2];          // partial sums from GEMM epilogues
__device__ __nv_bfloat16 g_Whi[768 * 256], g_Wlo[768 * 256];
__device__ __nv_bfloat16 g_Wphi[256 * 256], g_Wplo[256 * 256];
__device__ __nv_bfloat16 g_Xhi[(size_t)NTOK * 256], g_Xlo[(size_t)NTOK * 256];
__device__ __nv_bfloat16 g_Uhi[(size_t)NTOK * 256], g_Ulo[(size_t)NTOK * 256];

// ---------------- helpers ------------------------------------------------------
__device__ __forceinline__ uint32_t smem_u32(const void* p) {
    return (uint32_t)__cvta_generic_to_shared(p);
}
__device__ __forceinline__ unsigned short f2bf_us(float v) {
    __nv_bfloat16 b = __float2bfloat16(v);
    return *reinterpret_cast<unsigned short*>(&b);
}
__device__ __forceinline__ void cp_async16(uint32_t s, const void* g) {
    asm volatile("cp.async.cg.shared.global [%0], [%1], 16;" :: "r"(s), "l"(g));
}
__device__ __forceinline__ void cp_commit() {
    asm volatile("cp.async.commit_group;");
}
__device__ __forceinline__ void ldsm_x4(uint32_t* r, uint32_t a) {
    asm volatile("ldmatrix.sync.aligned.m8n8.x4.shared.b16 {%0,%1,%2,%3}, [%4];"
                 : "=r"(r[0]), "=r"(r[1]), "=r"(r[2]), "=r"(r[3]) : "r"(a));
}
__device__ __forceinline__ void ldsm_x2(uint32_t* r, uint32_t a) {
    asm volatile("ldmatrix.sync.aligned.m8n8.x2.shared.b16 {%0,%1}, [%2];"
                 : "=r"(r[0]), "=r"(r[1]) : "r"(a));
}
__device__ __forceinline__ void mma_bf16(float* c, const uint32_t* a, const uint32_t* b) {
    asm volatile(
        "mma.sync.aligned.m16n8k16.row.col.f32.bf16.bf16.f32 "
        "{%0,%1,%2,%3}, {%4,%5,%6,%7}, {%8,%9}, {%0,%1,%2,%3};"
        : "+f"(c[0]), "+f"(c[1]), "+f"(c[2]), "+f"(c[3])
        : "r"(a[0]), "r"(a[1]), "r"(a[2]), "r"(a[3]), "r"(b[0]), "r"(b[1]));
}

// ---------------- W -> bf16 hi/lo (K-major already) ---------------------------
__global__ void convert_w_kernel(const float* __restrict__ wq, const float* __restrict__ wk,
                                 const float* __restrict__ wv, const float* __restrict__ wp) {
    int i = blockIdx.x * 256 + threadIdx.x;  // 0..262143
    float v;
    __nv_bfloat16 *hi, *lo;
    int o;
    if (i < 65536)        { v = wq[i];          o = i;          hi = g_Whi;  lo = g_Wlo; }
    else if (i < 131072)  { v = wk[i - 65536];  o = i;          hi = g_Whi;  lo = g_Wlo; }
    else if (i < 196608)  { v = wv[i - 131072]; o = i;          hi = g_Whi;  lo = g_Wlo; }
    else                  { v = wp[i - 196608]; o = i - 196608; hi = g_Wphi; lo = g_Wplo; }
    __nv_bfloat16 h = __float2bfloat16(v);
    hi[o] = h;
    lo[o] = __float2bfloat16(v - __bfloat162float(h));
}

// ---------------- transpose [c][hw] fp32 -> token-major bf16 hi/lo -------------
__global__ void transpose_convert_kernel(const float* __restrict__ src, int c_stride, int b_stride,
                                         __nv_bfloat16* __restrict__ dhi,
                                         __nv_bfloat16* __restrict__ dlo) {
    __shared__ float t[32][33];
    const int hw0 = blockIdx.x * 32, c0 = blockIdx.y * 32, b = blockIdx.z;
    const int tid = threadIdx.x;
    const int rl = tid >> 3, q = tid & 7;
    float4 v = *(const float4*)(src + (size_t)b * b_stride + (size_t)(c0 + rl) * c_stride + hw0 + q * 4);
    t[rl][q * 4 + 0] = v.x; t[rl][q * 4 + 1] = v.y;
    t[rl][q * 4 + 2] = v.z; t[rl][q * 4 + 3] = v.w;
    __syncthreads();
    const int n = b * HWN + hw0 + rl;
    ushort4 hs, ls;
    float f0 = t[q * 4 + 0][rl], f1 = t[q * 4 + 1][rl];
    float f2 = t[q * 4 + 2][rl], f3 = t[q * 4 + 3][rl];
    hs.x = f2bf_us(f0); hs.y = f2bf_us(f1); hs.z = f2bf_us(f2); hs.w = f2bf_us(f3);
    ls.x = f2bf_us(f0 - __bfloat162float(__float2bfloat16(f0)));
    ls.y = f2bf_us(f1 - __bfloat162float(__float2bfloat16(f1)));
    ls.z = f2bf_us(f2 - __bfloat162float(__float2bfloat16(f2)));
    ls.w = f2bf_us(f3 - __bfloat162float(__float2bfloat16(f3)));
    *(ushort4*)(dhi + (size_t)n * 256 + c0 + q * 4) = hs;
    *(ushort4*)(dlo + (size_t)n * 256 + c0 + q * 4) = ls;
}

// ---------------- mma.sync GEMM + fused GN stats partials ----------------------
// gemm_id 0: QKV (by 0-1 q -> slot 0, by 2-3 k -> slot 1, by 4-5 v -> none)
// gemm_id 1: output proj -> slot 2
__global__ __launch_bounds__(256) void mma_gemm_kernel(
    const __nv_bfloat16* __restrict__ Ahi, const __nv_bfloat16* __restrict__ Alo,
    const __nv_bfloat16* __restrict__ Bhi, const __nv_bfloat16* __restrict__ Blo,
    float* __restrict__ out, const float* __restrict__ bias, int gemm_id) {
    __shared__ __nv_bfloat16 As[2][128 * LDT];
    __shared__ __nv_bfloat16 Bs[2][128 * LDT];
    __shared__ float sred[8][4];
    const int tid = threadIdx.x;
    const int lane = tid & 31;
    const int wid = tid >> 5;
    const int wm = wid >> 2;          // 0..1
    const int wn = wid & 3;           // 0..3
    const int m0 = blockIdx.y * 128;
    const int n0 = blockIdx.x * 128;
    const int NITER = 24;             // 3 passes x 8

    float acc[4][4][4];
#pragma unroll
    for (int i = 0; i < 4; i++)
#pragma unroll
        for (int j = 0; j < 4; j++)
#pragma unroll
            for (int r = 0; r < 4; r++) acc[i][j][r] = 0.f;

    const int lrow = tid >> 1;            // 0..127
    const int lch2 = (tid & 1) * 2;       // chunk pairs {0,1} or {2,3}

#define LOAD_TILE(buf, kc)                                                              \
    do {                                                                                \
        int p = (kc) >> 3, k0 = ((kc) & 7) * 32;                                        \
        const __nv_bfloat16* ga = ((p == 2) ? Alo : Ahi) + (size_t)(m0 + lrow) * 256 + k0; \
        const __nv_bfloat16* gb = ((p == 1) ? Blo : Bhi) + (size_t)(n0 + lrow) * 256 + k0; \
        uint32_t sa = smem_u32(&As[buf][lrow * LDT + lch2 * 8]);                        \
        uint32_t sb = smem_u32(&Bs[buf][lrow * LDT + lch2 * 8]);                        \
        cp_async16(sa,      ga + lch2 * 8);                                             \
        cp_async16(sa + 16, ga + lch2 * 8 + 8);                                         \
        cp_async16(sb,      gb + lch2 * 8);                                             \
        cp_async16(sb + 16, gb + lch2 * 8 + 8);                                         \
        cp_commit();                                                                    \
    } while (0)

    LOAD_TILE(0, 0);

    int buf = 0;
    for (int kc = 0; kc < NITER; kc++) {
        if (kc + 1 < NITER) {
            LOAD_TILE(buf ^ 1, kc + 1);
            asm volatile("cp.async.wait_group 1;");
        } else {
            asm volatile("cp.async.wait_group 0;");
        }
        __syncthreads();

#pragma unroll
        for (int ks = 0; ks < 2; ks++) {
            uint32_t afr[4][4];
#pragma unroll
            for (int i = 0; i < 4; i++) {
                uint32_t a = smem_u32(&As[buf][(wm * 64 + i * 16 + (lane & 15)) * LDT +
                                              ((lane >> 4) * 8 + ks * 16)]);
                ldsm_x4(afr[i], a);
            }
            uint32_t bfr[4][2];
#pragma unroll
            for (int j = 0; j < 4; j++) {
                int l2 = lane & 15;
                uint32_t a = smem_u32(&Bs[buf][(wn * 32 + j * 8 + (l2 & 7)) * LDT +
                                              (((l2 >> 3) & 1) * 8 + ks * 16)]);
                ldsm_x2(bfr[j], a);
            }
#pragma unroll
            for (int i = 0; i < 4; i++)
#pragma unroll
                for (int j = 0; j < 4; j++) mma_bf16(acc[i][j], afr[i], bfr[j]);
        }
        __syncthreads();
        buf ^= 1;
    }
#undef LOAD_TILE

    // epilogue: stores + per-group stats accumulation
    float s[2] = {0.f, 0.f}, s2[2] = {0.f, 0.f};
#pragma unroll
    for (int i = 0; i < 4; i++) {
        const int row = m0 + wm * 64 + i * 16 + (lane >> 2);
        const int gh = i >> 1;
        const float b0v = bias ? bias[row] : 0.f;
        const float b1v = bias ? bias[row + 8] : 0.f;
#pragma unroll
        for (int j = 0; j < 4; j++) {
            const int col = n0 + wn * 32 + j * 8 + (lane & 3) * 2;
            float v0x = acc[i][j][0] + b0v, v0y = acc[i][j][1] + b0v;
            float v1x = acc[i][j][2] + b1v, v1y = acc[i][j][3] + b1v;
            s[gh] += (v0x + v0y) + (v1x + v1y);
            s2[gh] += v0x * v0x + v0y * v0y + v1x * v1x + v1y * v1y;
            *(float2*)(out + (size_t)row * NTOK + col) = make_float2(v0x, v0y);
            *(float2*)(out + (size_t)(row + 8) * NTOK + col) = make_float2(v1x, v1y);
        }
    }

    // slot selection
    int slot = (gemm_id == 0) ? ((blockIdx.y < 4) ? (int)(blockIdx.y >> 1) : -1) : 2;
    if (slot < 0) return;
    const int group_base = (gemm_id == 0) ? (blockIdx.y & 1) * 4 : blockIdx.y * 4;

#pragma unroll
    for (int off = 16; off > 0; off >>= 1) {
        s[0] += __shfl_xor_sync(0xffffffffu, s[0], off);
        s[1] += __shfl_xor_sync(0xffffffffu, s[1], off);
        s2[0] += __shfl_xor_sync(0xffffffffu, s2[0], off);
        s2[1] += __shfl_xor_sync(0xffffffffu, s2[1], off);
    }
    if (lane == 0) {
        sred[wid][0] = s[0]; sred[wid][1] = s[1];
        sred[wid][2] = s2[0]; sred[wid][3] = s2[1];
    }
    __syncthreads();
    if (tid < 4) {
        const int wmm = tid >> 1, gh = tid & 1;
        float ss = 0.f, ss2 = 0.f;
#pragma unroll
        for (int w = 0; w < 4; w++) {
            ss += sred[wmm * 4 + w][gh];
            ss2 += sred[wmm * 4 + w][2 + gh];
        }
        const int b = blockIdx.x >> 5;
        const int bxl = blockIdx.x & 31;
        const int pair = b * 8 + group_base + wmm * 2 + gh;
        g_part[slot][pair][bxl][0] = ss;
        g_part[slot][pair][bxl][1] = ss2;
    }
}

// ---------------- GN stats finalize --------------------------------------------
__global__ void gn_finalize_kernel(int first) {
    const int slot = first + blockIdx.x;
    const int pair = threadIdx.x;  // 0..31
    float s = 0.f, s2 = 0.f;
#pragma unroll
    for (int p = 0; p < NPART; p++) {
        s += g_part[slot][pair][p][0];
        s2 += g_part[slot][pair][p][1];
    }
    const float inv = 1.f / 131072.f;
    float mean = s * inv;
    float var = s2 * inv - mean * mean;
    g_stats[(slot * 32 + pair) * 2 + 0] = mean;
    g_stats[(slot * 32 + pair) * 2 + 1] = rsqrtf(var + EPS_GN);
}

// ---------------- fused depthwise conv 3x3 + GeLU + conv 3x3 -------------------
__global__ __launch_bounds__(256) void dwconv_fused_kernel(
    const float* __restrict__ x,
    const float* __restrict__ dw1, const float* __restrict__ db1,
    const float* __restrict__ dw2, const float* __restrict__ db2) {
    __shared__ float xs[64 * 64];
    __shared__ float p1[64 * 65];
    const int bc = blockIdx.x;          // b*256 + c
    const int c = bc & 255;
    const float* xb = x + (size_t)bc * HWN;
    const int tid = threadIdx.x;

#pragma unroll
    for (int i = 0; i < 4; i++) {
        int idx = tid + i * 256;
        *(float4*)&xs[idx * 4] = *(const float4*)(xb + idx * 4);
    }
    float w1[9], w2[9];
#pragma unroll
    for (int i = 0; i < 9; i++) { w1[i] = dw1[c * 9 + i]; w2[i] = dw2[c * 9 + i]; }
    const float b1 = db1[c], b2 = db2[c];
    __syncthreads();

#pragma unroll
    for (int i = 0; i < 16; i++) {
        int idx = tid + i * 256;
        int px = idx & 63, py = idx >> 6;
        float acc = b1;
#pragma unroll
        for (int dy = -1; dy <= 1; dy++) {
            int yy = py + dy;
            if ((unsigned)yy > 63u) continue;
#pragma unroll
            for (int dx = -1; dx <= 1; dx++) {
                int xx = px + dx;
                if ((unsigned)xx > 63u) continue;
                acc = fmaf(xs[yy * 64 + xx], w1[(dy + 1) * 3 + (dx + 1)], acc);
            }
        }
        p1[py * 65 + px] = 0.5f * acc * (1.f + erff(acc * 0.70710678118654752f));
    }
    __syncthreads();

#pragma unroll
    for (int i = 0; i < 16; i++) {
        int idx = tid + i * 256;
        int px = idx & 63, py = idx >> 6;
        float acc = b2;
#pragma unroll
        for (int dy = -1; dy <= 1; dy++) {
            int yy = py + dy;
            if ((unsigned)yy > 63u) continue;
#pragma unroll
            for (int dx = -1; dx <= 1; dx++) {
                int xx = px + dx;
                if ((unsigned)xx > 63u) continue;
                acc = fmaf(p1[yy * 65 + xx], w2[(dy + 1) * 3 + (dx + 1)], acc);
            }
        }
        g_pos[(size_t)bc * HWN + idx] = acc;
    }
}

// ---------------- attention + residual + bf16 split emission -------------------
__global__ __launch_bounds__(1024) void attn_kernel(
    const float* __restrict__ gqg, const float* __restrict__ gqb,
    const float* __restrict__ gkg, const float* __restrict__ gkb) {
    extern __shared__ float smf[];
    float* smq = smf;                 // [256][33]
    float* smk = smf + 256 * 33;
    float* smv = smf + 2 * 256 * 33;
    float* smp = smf + 3 * 256 * 33;  // pos tile
    float* kv  = smf + 4 * 256 * 33;  // [32 warps][64]: interleaved (k,v)
    const int tid = threadIdx.x;
    const int warp = tid >> 5;
    const int lane = tid & 31;
    const int n0 = blockIdx.x * 32;
    const int b = n0 >> 12;
    const int hw0 = n0 & 4095;

#pragma unroll
    for (int r = 0; r < 6; r++) {
        const int tens = r >> 1;
        const int slot = tid + r * 1024;
        const int row = (slot >> 3) & 255;
        const int q8 = slot & 7;
        float4 v = *(const float4*)(g_Y + (size_t)(tens * 256 + row) * NTOK + n0 + q8 * 4);
        float* dst = smf + tens * (256 * 33) + row * 33 + q8 * 4;
        dst[0] = v.x; dst[1] = v.y; dst[2] = v.z; dst[3] = v.w;
    }
#pragma unroll
    for (int r = 0; r < 2; r++) {
        const int slot = tid + r * 1024;
        const int row = (slot >> 3) & 255;
        const int q8 = slot & 7;
        float4 v = *(const float4*)(g_pos + (size_t)b * CHW + (size_t)row * HWN + hw0 + q8 * 4);
        float* dst = smp + row * 33 + q8 * 4;
        dst[0] = v.x; dst[1] = v.y; dst[2] = v.z; dst[3] = v.w;
    }
    __syncthreads();

    const float scale_l2e = 0.17677669529663687f * 1.4426950408889634f;
    float oacc[8];
#pragma unroll 1
    for (int h = 0; h < 8; h++) {
        const int c = h * 32 + lane;
        float q = smq[c * 33 + warp];
        float k = smk[c * 33 + warp];
        float vv = smv[c * 33 + warp];
        const int qi = (b * 8 + h) * 2;
        const int ki = (32 + b * 8 + h) * 2;
        q = (q - g_stats[qi]) * g_stats[qi + 1] * gqg[c] + gqb[c];
        k = (k - g_stats[ki]) * g_stats[ki + 1] * gkg[c] + gkb[c];
        float sq = q * q, sk = k * k;
#pragma unroll
        for (int off = 16; off > 0; off >>= 1) {
            sq += __shfl_xor_sync(0xffffffffu, sq, off);
            sk += __shfl_xor_sync(0xffffffffu, sk, off);
        }
        const float qn = q / fmaxf(sqrtf(sq), 1e-12f);
        const float kn = k / fmaxf(sqrtf(sk), 1e-12f);
        __syncwarp();
        *(float2*)&kv[warp * 64 + lane * 2] = make_float2(kn, vv);
        __syncwarp();
        const float s2 = qn * scale_l2e;
        float num = 0.f, den = 0.f;
#pragma unroll
        for (int e = 0; e < 32; e++) {
            float2 kvp = *(const float2*)&kv[warp * 64 + e * 2];
            float t = s2 * kvp.x;
            float w;
            asm("ex2.approx.f32 %0, %1;" : "=f"(w) : "f"(t));
            den += w;
            num = fmaf(w, kvp.y, num);
        }
        oacc[h] = num / den + smp[c * 33 + warp];
    }
#pragma unroll
    for (int h = 0; h < 8; h++) smq[(h * 32 + lane) * 33 + warp] = oacc[h];
    __syncthreads();

#pragma unroll
    for (int it = 0; it < 2; it++) {
        const int j = (tid >> 6) + it * 16;   // token 0..31
        const int c0 = (tid & 63) * 4;
        float f0 = smq[(c0 + 0) * 33 + j];
        float f1 = smq[(c0 + 1) * 33 + j];
        float f2 = smq[(c0 + 2) * 33 + j];
        float f3 = smq[(c0 + 3) * 33 + j];
        ushort4 hs, ls;
        hs.x = f2bf_us(f0); hs.y = f2bf_us(f1); hs.z = f2bf_us(f2); hs.w = f2bf_us(f3);
        ls.x = f2bf_us(f0 - __bfloat162float(__float2bfloat16(f0)));
        ls.y = f2bf_us(f1 - __bfloat162float(__float2bfloat16(f1)));
        ls.z = f2bf_us(f2 - __bfloat162float(__float2bfloat16(f2)));
        ls.w = f2bf_us(f3 - __bfloat162float(__float2bfloat16(f3)));
        const size_t n = (size_t)(n0 + j);
        *(ushort4*)(g_Uhi + n * 256 + c0) = hs;
        *(ushort4*)(g_Ulo + n * 256 + c0) = ls;
    }
}

// ---------------- final GN apply (float4, channel-major in, NCHW out) ----------
__global__ void gn_apply_kernel(const float* __restrict__ gamma,
                                const float* __restrict__ beta,
                                float* __restrict__ out) {
    int idx4 = blockIdx.x * 256 + threadIdx.x;  // over 256*16384/4
    const int c = idx4 >> 12;
    const int n = (idx4 & 4095) * 4;
    const int b = n >> 12;
    const int g = c >> 5;
    const int si = (2 * 32 + b * 8 + g) * 2;
    const float mean = g_stats[si], rstd = g_stats[si + 1];
    const float ga = gamma[c], be = beta[c];
    float4 v = *(const float4*)(g_Z + (size_t)idx4 * 4);
    v.x = (v.x - mean) * rstd * ga + be;
    v.y = (v.y - mean) * rstd * ga + be;
    v.z = (v.z - mean) * rstd * ga + be;
    v.w = (v.w - mean) * rstd * ga + be;
    *(float4*)(out + (size_t)b * CHW + (size_t)c * HWN + (n & 4095)) = v;
}

// ---------------- launcher -----------------------------------------------------
extern "C" void kernel_launch(void* const* d_in, const int* in_sizes, int n_in,
                              void* d_out, int out_size) {
    const float* x        = (const float*)d_in[0];
    const float* wq       = (const float*)d_in[1];
    const float* gq_gamma = (const float*)d_in[2];
    const float* gq_beta  = (const float*)d_in[3];
    const float* wk       = (const float*)d_in[4];
    const float* gk_gamma = (const float*)d_in[5];
    const float* gk_beta  = (const float*)d_in[6];
    const float* wv       = (const float*)d_in[7];
    const float* wp       = (const float*)d_in[8];
    const float* bp       = (const float*)d_in[9];
    const float* gp_gamma = (const float*)d_in[10];
    const float* gp_beta  = (const float*)d_in[11];
    const float* dw1      = (const float*)d_in[12];
    const float* db1      = (const float*)d_in[13];
    const float* dw2      = (const float*)d_in[14];
    const float* db2      = (const float*)d_in[15];
    float* out = (float*)d_out;

    static bool attr_set = false;
    if (!attr_set) {
        cudaFuncSetAttribute(attn_kernel, cudaFuncAttributeMaxDynamicSharedMemorySize, 143360);
        attr_set = true;
    }

    float *g_Y_p, *g_Z_p;
    __nv_bfloat16 *whi, *wlo, *wphi, *wplo, *xhi, *xlo, *uhi, *ulo;
    cudaGetSymbolAddress((void**)&g_Y_p, g_Y);
    cudaGetSymbolAddress((void**)&g_Z_p, g_Z);
    cudaGetSymbolAddress((void**)&whi, g_Whi);
    cudaGetSymbolAddress((void**)&wlo, g_Wlo);
    cudaGetSymbolAddress((void**)&wphi, g_Wphi);
    cudaGetSymbolAddress((void**)&wplo, g_Wplo);
    cudaGetSymbolAddress((void**)&xhi, g_Xhi);
    cudaGetSymbolAddress((void**)&xlo, g_Xlo);
    cudaGetSymbolAddress((void**)&uhi, g_Uhi);
    cudaGetSymbolAddress((void**)&ulo, g_Ulo);

    // 1. weight + input conversion
    convert_w_kernel<<<1024, 256>>>(wq, wk, wv, wp);
    transpose_convert_kernel<<<dim3(128, 8, BATCH), 256>>>(x, HWN, CHW, xhi, xlo);
    // 2. QKV GEMM (stats for q,k fused into epilogue) -> g_Y [768][16384]
    mma_gemm_kernel<<<dim3(128, 6), 256>>>(whi, wlo, xhi, xlo, g_Y_p, nullptr, 0);
    gn_finalize_kernel<<<2, 32>>>(0);
    // 3. fused positional path -> g_pos
    dwconv_fused_kernel<<<1024, 256>>>(x, dw1, db1, dw2, db2);
    // 4. attention + residual -> U bf16 hi/lo (token-major) directly
    attn_kernel<<<512, 1024, 143360>>>(gq_gamma, gq_beta, gk_gamma, gk_beta);
    // 5. output projection GEMM (stats fused) -> g_Z [256][16384]
    mma_gemm_kernel<<<dim3(128, 2), 256>>>(wphi, wplo, uhi, ulo, g_Z_p, bp, 1);
    gn_finalize_kernel<<<1, 32>>>(2);
    // 6. final group norm apply
    gn_apply_kernel<<<NTOK * 256 / 1024, 256>>>(gp_gamma, gp_beta, out);
}

// round 7
// speedup vs baseline: 1.8141x; 1.0694x over previous
#include <cuda_runtime.h>
#include <cuda_bf16.h>
#include <math.h>
#include <stdint.h>

#define BATCH 4
#define CCH 256
#define HWN 4096
#define NTOK 16384          // BATCH*HWN
#define CHW (CCH*HWN)
#define TOTAL (BATCH*CHW)
#define EPS_GN 1e-5f
#define LDT 40              // padded smem row length (bf16) for 32-wide K tile
#define NPART 32            // n-tiles per batch (4096/128)

// ---------------- scratch (device globals) ------------------------------------
__device__ float g_Y[(size_t)768 * NTOK];          // [768][16384] q|k|v channel-major
__device__ float g_pos[TOTAL];                     // NCHW positional branch output
__device__ float g_Z[(size_t)CCH * NTOK];          // [256][16384] channel-major
__device__ float g_stats[3 * 32 * 2];              // [slot q/k/z][b*8+g][mean,rstd]
__device__ float g_part[3][32][NPART][2];          // partial sums from GEMM epilogues
__device__ __nv_bfloat16 g_Whi[768 * 256], g_Wlo[768 * 256];
__device__ __nv_bfloat16 g_Wphi[256 * 256], g_Wplo[256 * 256];
__device__ __nv_bfloat16 g_Xhi[(size_t)NTOK * 256], g_Xlo[(size_t)NTOK * 256];
__device__ __nv_bfloat16 g_Uhi[(size_t)NTOK * 256], g_Ulo[(size_t)NTOK * 256];

// ---------------- helpers ------------------------------------------------------
__device__ __forceinline__ uint32_t smem_u32(const void* p) {
    return (uint32_t)__cvta_generic_to_shared(p);
}
__device__ __forceinline__ unsigned short f2bf_us(float v) {
    __nv_bfloat16 b = __float2bfloat16(v);
    return *reinterpret_cast<unsigned short*>(&b);
}
__device__ __forceinline__ void cp_async16(uint32_t s, const void* g) {
    asm volatile("cp.async.cg.shared.global [%0], [%1], 16;" :: "r"(s), "l"(g));
}
__device__ __forceinline__ void cp_commit() {
    asm volatile("cp.async.commit_group;");
}
__device__ __forceinline__ void ldsm_x4(uint32_t* r, uint32_t a) {
    asm volatile("ldmatrix.sync.aligned.m8n8.x4.shared.b16 {%0,%1,%2,%3}, [%4];"
                 : "=r"(r[0]), "=r"(r[1]), "=r"(r[2]), "=r"(r[3]) : "r"(a));
}
__device__ __forceinline__ void ldsm_x2(uint32_t* r, uint32_t a) {
    asm volatile("ldmatrix.sync.aligned.m8n8.x2.shared.b16 {%0,%1}, [%2];"
                 : "=r"(r[0]), "=r"(r[1]) : "r"(a));
}
__device__ __forceinline__ void mma_bf16(float* c, const uint32_t* a, const uint32_t* b) {
    asm volatile(
        "mma.sync.aligned.m16n8k16.row.col.f32.bf16.bf16.f32 "
        "{%0,%1,%2,%3}, {%4,%5,%6,%7}, {%8,%9}, {%0,%1,%2,%3};"
        : "+f"(c[0]), "+f"(c[1]), "+f"(c[2]), "+f"(c[3])
        : "r"(a[0]), "r"(a[1]), "r"(a[2]), "r"(a[3]), "r"(b[0]), "r"(b[1]));
}

// ---------------- W -> bf16 hi/lo (K-major already) ---------------------------
__global__ void convert_w_kernel(const float* __restrict__ wq, const float* __restrict__ wk,
                                 const float* __restrict__ wv, const float* __restrict__ wp) {
    int i = blockIdx.x * 256 + threadIdx.x;  // 0..262143
    float v;
    __nv_bfloat16 *hi, *lo;
    int o;
    if (i < 65536)        { v = wq[i];          o = i;          hi = g_Whi;  lo = g_Wlo; }
    else if (i < 131072)  { v = wk[i - 65536];  o = i;          hi = g_Whi;  lo = g_Wlo; }
    else if (i < 196608)  { v = wv[i - 131072]; o = i;          hi = g_Whi;  lo = g_Wlo; }
    else                  { v = wp[i - 196608]; o = i - 196608; hi = g_Wphi; lo = g_Wplo; }
    __nv_bfloat16 h = __float2bfloat16(v);
    hi[o] = h;
    lo[o] = __float2bfloat16(v - __bfloat162float(h));
}

// ---------------- transpose [c][hw] fp32 -> token-major bf16 hi/lo -------------
__global__ void transpose_convert_kernel(const float* __restrict__ src, int c_stride, int b_stride,
                                         __nv_bfloat16* __restrict__ dhi,
                                         __nv_bfloat16* __restrict__ dlo) {
    __shared__ float t[32][33];
    const int hw0 = blockIdx.x * 32, c0 = blockIdx.y * 32, b = blockIdx.z;
    const int tid = threadIdx.x;
    const int rl = tid >> 3, q = tid & 7;
    float4 v = *(const float4*)(src + (size_t)b * b_stride + (size_t)(c0 + rl) * c_stride + hw0 + q * 4);
    t[rl][q * 4 + 0] = v.x; t[rl][q * 4 + 1] = v.y;
    t[rl][q * 4 + 2] = v.z; t[rl][q * 4 + 3] = v.w;
    __syncthreads();
    const int n = b * HWN + hw0 + rl;
    ushort4 hs, ls;
    float f0 = t[q * 4 + 0][rl], f1 = t[q * 4 + 1][rl];
    float f2 = t[q * 4 + 2][rl], f3 = t[q * 4 + 3][rl];
    hs.x = f2bf_us(f0); hs.y = f2bf_us(f1); hs.z = f2bf_us(f2); hs.w = f2bf_us(f3);
    ls.x = f2bf_us(f0 - __bfloat162float(__float2bfloat16(f0)));
    ls.y = f2bf_us(f1 - __bfloat162float(__float2bfloat16(f1)));
    ls.z = f2bf_us(f2 - __bfloat162float(__float2bfloat16(f2)));
    ls.w = f2bf_us(f3 - __bfloat162float(__float2bfloat16(f3)));
    *(ushort4*)(dhi + (size_t)n * 256 + c0 + q * 4) = hs;
    *(ushort4*)(dlo + (size_t)n * 256 + c0 + q * 4) = ls;
}

// ---------------- mma.sync GEMM + fused GN stats partials ----------------------
__global__ __launch_bounds__(256) void mma_gemm_kernel(
    const __nv_bfloat16* __restrict__ Ahi, const __nv_bfloat16* __restrict__ Alo,
    const __nv_bfloat16* __restrict__ Bhi, const __nv_bfloat16* __restrict__ Blo,
    float* __restrict__ out, const float* __restrict__ bias, int gemm_id) {
    __shared__ __nv_bfloat16 As[2][128 * LDT];
    __shared__ __nv_bfloat16 Bs[2][128 * LDT];
    __shared__ float sred[8][4];
    const int tid = threadIdx.x;
    const int lane = tid & 31;
    const int wid = tid >> 5;
    const int wm = wid >> 2;          // 0..1
    const int wn = wid & 3;           // 0..3
    const int m0 = blockIdx.y * 128;
    const int n0 = blockIdx.x * 128;
    const int NITER = 24;             // 3 passes x 8

    float acc[4][4][4];
#pragma unroll
    for (int i = 0; i < 4; i++)
#pragma unroll
        for (int j = 0; j < 4; j++)
#pragma unroll
            for (int r = 0; r < 4; r++) acc[i][j][r] = 0.f;

    const int lrow = tid >> 1;
    const int lch2 = (tid & 1) * 2;

#define LOAD_TILE(buf, kc)                                                              \
    do {                                                                                \
        int p = (kc) >> 3, k0 = ((kc) & 7) * 32;                                        \
        const __nv_bfloat16* ga = ((p == 2) ? Alo : Ahi) + (size_t)(m0 + lrow) * 256 + k0; \
        const __nv_bfloat16* gb = ((p == 1) ? Blo : Bhi) + (size_t)(n0 + lrow) * 256 + k0; \
        uint32_t sa = smem_u32(&As[buf][lrow * LDT + lch2 * 8]);                        \
        uint32_t sb = smem_u32(&Bs[buf][lrow * LDT + lch2 * 8]);                        \
        cp_async16(sa,      ga + lch2 * 8);                                             \
        cp_async16(sa + 16, ga + lch2 * 8 + 8);                                         \
        cp_async16(sb,      gb + lch2 * 8);                                             \
        cp_async16(sb + 16, gb + lch2 * 8 + 8);                                         \
        cp_commit();                                                                    \
    } while (0)

    LOAD_TILE(0, 0);

    int buf = 0;
    for (int kc = 0; kc < NITER; kc++) {
        if (kc + 1 < NITER) {
            LOAD_TILE(buf ^ 1, kc + 1);
            asm volatile("cp.async.wait_group 1;");
        } else {
            asm volatile("cp.async.wait_group 0;");
        }
        __syncthreads();

#pragma unroll
        for (int ks = 0; ks < 2; ks++) {
            uint32_t afr[4][4];
#pragma unroll
            for (int i = 0; i < 4; i++) {
                uint32_t a = smem_u32(&As[buf][(wm * 64 + i * 16 + (lane & 15)) * LDT +
                                              ((lane >> 4) * 8 + ks * 16)]);
                ldsm_x4(afr[i], a);
            }
            uint32_t bfr[4][2];
#pragma unroll
            for (int j = 0; j < 4; j++) {
                int l2 = lane & 15;
                uint32_t a = smem_u32(&Bs[buf][(wn * 32 + j * 8 + (l2 & 7)) * LDT +
                                              (((l2 >> 3) & 1) * 8 + ks * 16)]);
                ldsm_x2(bfr[j], a);
            }
#pragma unroll
            for (int i = 0; i < 4; i++)
#pragma unroll
                for (int j = 0; j < 4; j++) mma_bf16(acc[i][j], afr[i], bfr[j]);
        }
        __syncthreads();
        buf ^= 1;
    }
#undef LOAD_TILE

    float s[2] = {0.f, 0.f}, s2[2] = {0.f, 0.f};
#pragma unroll
    for (int i = 0; i < 4; i++) {
        const int row = m0 + wm * 64 + i * 16 + (lane >> 2);
        const int gh = i >> 1;
        const float b0v = bias ? bias[row] : 0.f;
        const float b1v = bias ? bias[row + 8] : 0.f;
#pragma unroll
        for (int j = 0; j < 4; j++) {
            const int col = n0 + wn * 32 + j * 8 + (lane & 3) * 2;
            float v0x = acc[i][j][0] + b0v, v0y = acc[i][j][1] + b0v;
            float v1x = acc[i][j][2] + b1v, v1y = acc[i][j][3] + b1v;
            s[gh] += (v0x + v0y) + (v1x + v1y);
            s2[gh] += v0x * v0x + v0y * v0y + v1x * v1x + v1y * v1y;
            *(float2*)(out + (size_t)row * NTOK + col) = make_float2(v0x, v0y);
            *(float2*)(out + (size_t)(row + 8) * NTOK + col) = make_float2(v1x, v1y);
        }
    }

    int slot = (gemm_id == 0) ? ((blockIdx.y < 4) ? (int)(blockIdx.y >> 1) : -1) : 2;
    if (slot < 0) return;
    const int group_base = (gemm_id == 0) ? (blockIdx.y & 1) * 4 : blockIdx.y * 4;

#pragma unroll
    for (int off = 16; off > 0; off >>= 1) {
        s[0] += __shfl_xor_sync(0xffffffffu, s[0], off);
        s[1] += __shfl_xor_sync(0xffffffffu, s[1], off);
        s2[0] += __shfl_xor_sync(0xffffffffu, s2[0], off);
        s2[1] += __shfl_xor_sync(0xffffffffu, s2[1], off);
    }
    if (lane == 0) {
        sred[wid][0] = s[0]; sred[wid][1] = s[1];
        sred[wid][2] = s2[0]; sred[wid][3] = s2[1];
    }
    __syncthreads();
    if (tid < 4) {
        const int wmm = tid >> 1, gh = tid & 1;
        float ss = 0.f, ss2 = 0.f;
#pragma unroll
        for (int w = 0; w < 4; w++) {
            ss += sred[wmm * 4 + w][gh];
            ss2 += sred[wmm * 4 + w][2 + gh];
        }
        const int b = blockIdx.x >> 5;
        const int bxl = blockIdx.x & 31;
        const int pair = b * 8 + group_base + wmm * 2 + gh;
        g_part[slot][pair][bxl][0] = ss;
        g_part[slot][pair][bxl][1] = ss2;
    }
}

// ---------------- GN stats finalize: warp per pair -----------------------------
// grid: (32 pairs, nslots); 32 threads, lane = part.
__global__ void gn_finalize_kernel(int first) {
    const int slot = first + blockIdx.y;
    const int pair = blockIdx.x;
    const int lane = threadIdx.x;
    float s = g_part[slot][pair][lane][0];
    float s2 = g_part[slot][pair][lane][1];
#pragma unroll
    for (int off = 16; off > 0; off >>= 1) {
        s += __shfl_xor_sync(0xffffffffu, s, off);
        s2 += __shfl_xor_sync(0xffffffffu, s2, off);
    }
    if (lane == 0) {
        const float inv = 1.f / 131072.f;
        float mean = s * inv;
        float var = s2 * inv - mean * mean;
        g_stats[(slot * 32 + pair) * 2 + 0] = mean;
        g_stats[(slot * 32 + pair) * 2 + 1] = rsqrtf(var + EPS_GN);
    }
}

// ---------------- fused depthwise conv 3x3 + GeLU + conv 3x3 -------------------
__global__ __launch_bounds__(256) void dwconv_fused_kernel(
    const float* __restrict__ x,
    const float* __restrict__ dw1, const float* __restrict__ db1,
    const float* __restrict__ dw2, const float* __restrict__ db2) {
    __shared__ float xs[64 * 64];
    __shared__ float p1[64 * 65];
    const int bc = blockIdx.x;          // b*256 + c
    const int c = bc & 255;
    const float* xb = x + (size_t)bc * HWN;
    const int tid = threadIdx.x;

#pragma unroll
    for (int i = 0; i < 4; i++) {
        int idx = tid + i * 256;
        *(float4*)&xs[idx * 4] = *(const float4*)(xb + idx * 4);
    }
    float w1[9], w2[9];
#pragma unroll
    for (int i = 0; i < 9; i++) { w1[i] = dw1[c * 9 + i]; w2[i] = dw2[c * 9 + i]; }
    const float b1 = db1[c], b2 = db2[c];
    __syncthreads();

#pragma unroll
    for (int i = 0; i < 16; i++) {
        int idx = tid + i * 256;
        int px = idx & 63, py = idx >> 6;
        float acc = b1;
#pragma unroll
        for (int dy = -1; dy <= 1; dy++) {
            int yy = py + dy;
            if ((unsigned)yy > 63u) continue;
#pragma unroll
            for (int dx = -1; dx <= 1; dx++) {
                int xx = px + dx;
                if ((unsigned)xx > 63u) continue;
                acc = fmaf(xs[yy * 64 + xx], w1[(dy + 1) * 3 + (dx + 1)], acc);
            }
        }
        p1[py * 65 + px] = 0.5f * acc * (1.f + erff(acc * 0.70710678118654752f));
    }
    __syncthreads();

#pragma unroll
    for (int i = 0; i < 16; i++) {
        int idx = tid + i * 256;
        int px = idx & 63, py = idx >> 6;
        float acc = b2;
#pragma unroll
        for (int dy = -1; dy <= 1; dy++) {
            int yy = py + dy;
            if ((unsigned)yy > 63u) continue;
#pragma unroll
            for (int dx = -1; dx <= 1; dx++) {
                int xx = px + dx;
                if ((unsigned)xx > 63u) continue;
                acc = fmaf(p1[yy * 65 + xx], w2[(dy + 1) * 3 + (dx + 1)], acc);
            }
        }
        g_pos[(size_t)bc * HWN + idx] = acc;
    }
}

// ---------------- attention via moment expansion + residual + bf16 emission ----
// softmax(q.k/sqrt(d)) has |arg| <= 1/sqrt(32); exp expanded to degree-4 Taylor.
// num_d = sum_m s_d^m/m! * B_m, B_m = sum_e k_e^m v_e (warp butterfly sums).
__global__ __launch_bounds__(1024) void attn_kernel(
    const float* __restrict__ gqg, const float* __restrict__ gqb,
    const float* __restrict__ gkg, const float* __restrict__ gkb) {
    extern __shared__ float smf[];
    float* smq = smf;                 // [256][33]
    float* smk = smf + 256 * 33;
    float* smv = smf + 2 * 256 * 33;
    float* smp = smf + 3 * 256 * 33;  // pos tile
    const int tid = threadIdx.x;
    const int warp = tid >> 5;
    const int lane = tid & 31;
    const int n0 = blockIdx.x * 32;
    const int b = n0 >> 12;
    const int hw0 = n0 & 4095;

#pragma unroll
    for (int r = 0; r < 6; r++) {
        const int tens = r >> 1;
        const int slot = tid + r * 1024;
        const int row = (slot >> 3) & 255;
        const int q8 = slot & 7;
        float4 v = *(const float4*)(g_Y + (size_t)(tens * 256 + row) * NTOK + n0 + q8 * 4);
        float* dst = smf + tens * (256 * 33) + row * 33 + q8 * 4;
        dst[0] = v.x; dst[1] = v.y; dst[2] = v.z; dst[3] = v.w;
    }
#pragma unroll
    for (int r = 0; r < 2; r++) {
        const int slot = tid + r * 1024;
        const int row = (slot >> 3) & 255;
        const int q8 = slot & 7;
        float4 v = *(const float4*)(g_pos + (size_t)b * CHW + (size_t)row * HWN + hw0 + q8 * 4);
        float* dst = smp + row * 33 + q8 * 4;
        dst[0] = v.x; dst[1] = v.y; dst[2] = v.z; dst[3] = v.w;
    }
    __syncthreads();

    const float scale = 0.17677669529663687f;  // 1/sqrt(32), natural exp
    float oacc[8];
#pragma unroll 1
    for (int h = 0; h < 8; h++) {
        const int c = h * 32 + lane;
        float q = smq[c * 33 + warp];
        float k = smk[c * 33 + warp];
        float vv = smv[c * 33 + warp];
        const int qi = (b * 8 + h) * 2;
        const int ki = (32 + b * 8 + h) * 2;
        q = (q - g_stats[qi]) * g_stats[qi + 1] * gqg[c] + gqb[c];
        k = (k - g_stats[ki]) * g_stats[ki + 1] * gkg[c] + gkb[c];
        float sq = q * q, sk = k * k;
#pragma unroll
        for (int off = 16; off > 0; off >>= 1) {
            sq += __shfl_xor_sync(0xffffffffu, sq, off);
            sk += __shfl_xor_sync(0xffffffffu, sk, off);
        }
        const float qn = q / fmaxf(sqrtf(sq), 1e-12f);
        const float kn = k / fmaxf(sqrtf(sk), 1e-12f);
        const float s = qn * scale;

        // moments (lane plays role e here)
        const float k2 = kn * kn;
        const float k3 = k2 * kn;
        const float k4 = k2 * k2;
        float a1 = kn, a2 = k2, a3 = k3, a4 = k4;
        float b0 = vv, b1m = kn * vv, b2 = k2 * vv, b3 = k3 * vv, b4 = k4 * vv;
#pragma unroll
        for (int off = 16; off > 0; off >>= 1) {
            a1 += __shfl_xor_sync(0xffffffffu, a1, off);
            a2 += __shfl_xor_sync(0xffffffffu, a2, off);
            a3 += __shfl_xor_sync(0xffffffffu, a3, off);
            a4 += __shfl_xor_sync(0xffffffffu, a4, off);
            b0 += __shfl_xor_sync(0xffffffffu, b0, off);
            b1m += __shfl_xor_sync(0xffffffffu, b1m, off);
            b2 += __shfl_xor_sync(0xffffffffu, b2, off);
            b3 += __shfl_xor_sync(0xffffffffu, b3, off);
            b4 += __shfl_xor_sync(0xffffffffu, b4, off);
        }
        // Horner: sum_m s^m/m! * X_m (lane plays role d here)
        const float c2 = 0.5f, c3 = 1.f / 6.f, c4 = 1.f / 24.f;
        float num = fmaf(s, fmaf(s, fmaf(s, fmaf(s, b4 * c4, b3 * c3), b2 * c2), b1m), b0);
        float den = fmaf(s, fmaf(s, fmaf(s, fmaf(s, a4 * c4, a3 * c3), a2 * c2), a1), 32.f);
        oacc[h] = __fdividef(num, den) + smp[c * 33 + warp];
    }
#pragma unroll
    for (int h = 0; h < 8; h++) smq[(h * 32 + lane) * 33 + warp] = oacc[h];
    __syncthreads();

#pragma unroll
    for (int it = 0; it < 2; it++) {
        const int j = (tid >> 6) + it * 16;   // token 0..31
        const int c0 = (tid & 63) * 4;
        float f0 = smq[(c0 + 0) * 33 + j];
        float f1 = smq[(c0 + 1) * 33 + j];
        float f2 = smq[(c0 + 2) * 33 + j];
        float f3 = smq[(c0 + 3) * 33 + j];
        ushort4 hs, ls;
        hs.x = f2bf_us(f0); hs.y = f2bf_us(f1); hs.z = f2bf_us(f2); hs.w = f2bf_us(f3);
        ls.x = f2bf_us(f0 - __bfloat162float(__float2bfloat16(f0)));
        ls.y = f2bf_us(f1 - __bfloat162float(__float2bfloat16(f1)));
        ls.z = f2bf_us(f2 - __bfloat162float(__float2bfloat16(f2)));
        ls.w = f2bf_us(f3 - __bfloat162float(__float2bfloat16(f3)));
        const size_t n = (size_t)(n0 + j);
        *(ushort4*)(g_Uhi + n * 256 + c0) = hs;
        *(ushort4*)(g_Ulo + n * 256 + c0) = ls;
    }
}

// ---------------- final GN apply (float4, channel-major in, NCHW out) ----------
__global__ void gn_apply_kernel(const float* __restrict__ gamma,
                                const float* __restrict__ beta,
                                float* __restrict__ out) {
    int idx4 = blockIdx.x * 256 + threadIdx.x;  // over 256*16384/4
    const int c = idx4 >> 12;
    const int n = (idx4 & 4095) * 4;
    const int b = n >> 12;
    const int g = c >> 5;
    const int si = (2 * 32 + b * 8 + g) * 2;
    const float mean = g_stats[si], rstd = g_stats[si + 1];
    const float ga = gamma[c], be = beta[c];
    float4 v = *(const float4*)(g_Z + (size_t)idx4 * 4);
    v.x = (v.x - mean) * rstd * ga + be;
    v.y = (v.y - mean) * rstd * ga + be;
    v.z = (v.z - mean) * rstd * ga + be;
    v.w = (v.w - mean) * rstd * ga + be;
    *(float4*)(out + (size_t)b * CHW + (size_t)c * HWN + (n & 4095)) = v;
}

// ---------------- launcher -----------------------------------------------------
extern "C" void kernel_launch(void* const* d_in, const int* in_sizes, int n_in,
                              void* d_out, int out_size) {
    const float* x        = (const float*)d_in[0];
    const float* wq       = (const float*)d_in[1];
    const float* gq_gamma = (const float*)d_in[2];
    const float* gq_beta  = (const float*)d_in[3];
    const float* wk       = (const float*)d_in[4];
    const float* gk_gamma = (const float*)d_in[5];
    const float* gk_beta  = (const float*)d_in[6];
    const float* wv       = (const float*)d_in[7];
    const float* wp       = (const float*)d_in[8];
    const float* bp       = (const float*)d_in[9];
    const float* gp_gamma = (const float*)d_in[10];
    const float* gp_beta  = (const float*)d_in[11];
    const float* dw1      = (const float*)d_in[12];
    const float* db1      = (const float*)d_in[13];
    const float* dw2      = (const float*)d_in[14];
    const float* db2      = (const float*)d_in[15];
    float* out = (float*)d_out;

    static bool attr_set = false;
    if (!attr_set) {
        cudaFuncSetAttribute(attn_kernel, cudaFuncAttributeMaxDynamicSharedMemorySize, 135168);
        attr_set = true;
    }

    float *g_Y_p, *g_Z_p;
    __nv_bfloat16 *whi, *wlo, *wphi, *wplo, *xhi, *xlo, *uhi, *ulo;
    cudaGetSymbolAddress((void**)&g_Y_p, g_Y);
    cudaGetSymbolAddress((void**)&g_Z_p, g_Z);
    cudaGetSymbolAddress((void**)&whi, g_Whi);
    cudaGetSymbolAddress((void**)&wlo, g_Wlo);
    cudaGetSymbolAddress((void**)&wphi, g_Wphi);
    cudaGetSymbolAddress((void**)&wplo, g_Wplo);
    cudaGetSymbolAddress((void**)&xhi, g_Xhi);
    cudaGetSymbolAddress((void**)&xlo, g_Xlo);
    cudaGetSymbolAddress((void**)&uhi, g_Uhi);
    cudaGetSymbolAddress((void**)&ulo, g_Ulo);

    // 1. weight + input conversion
    convert_w_kernel<<<1024, 256>>>(wq, wk, wv, wp);
    transpose_convert_kernel<<<dim3(128, 8, BATCH), 256>>>(x, HWN, CHW, xhi, xlo);
    // 2. QKV GEMM (stats for q,k fused into epilogue) -> g_Y [768][16384]
    mma_gemm_kernel<<<dim3(128, 6), 256>>>(whi, wlo, xhi, xlo, g_Y_p, nullptr, 0);
    gn_finalize_kernel<<<dim3(32, 2), 32>>>(0);
    // 3. fused positional path -> g_pos
    dwconv_fused_kernel<<<1024, 256>>>(x, dw1, db1, dw2, db2);
    // 4. attention + residual -> U bf16 hi/lo (token-major) directly
    attn_kernel<<<512, 1024, 135168>>>(gq_gamma, gq_beta, gk_gamma, gk_beta);
    // 5. output projection GEMM (stats fused) -> g_Z [256][16384]
    mma_gemm_kernel<<<dim3(128, 2), 256>>>(wphi, wplo, uhi, ulo, g_Z_p, bp, 1);
    gn_finalize_kernel<<<dim3(32, 1), 32>>>(2);
    // 6. final group norm apply
    gn_apply_kernel<<<NTOK * 256 / 1024, 256>>>(gp_gamma, gp_beta, out);
}

// round 8
// speedup vs baseline: 1.9019x; 1.0484x over previous
#include <cuda_runtime.h>
#include <cuda_bf16.h>
#include <math.h>
#include <stdint.h>

#define BATCH 4
#define CCH 256
#define HWN 4096
#define NTOK 16384          // BATCH*HWN
#define CHW (CCH*HWN)
#define TOTAL (BATCH*CHW)
#define EPS_GN 1e-5f
#define LDT 40              // padded smem row length (bf16) for 32-wide K tile
#define NPART 32            // n-tiles per batch (4096/128)

// ---------------- scratch (device globals) ------------------------------------
__device__ float g_Y[(size_t)768 * NTOK];          // [768][16384] q|k|v channel-major
__device__ float g_pos[TOTAL];                     // NCHW positional branch output
__device__ float g_Z[(size_t)CCH * NTOK];          // [256][16384] channel-major
__device__ float g_part[3][32][NPART][2];          // partial sums from GEMM epilogues
__device__ __nv_bfloat16 g_Whi[768 * 256], g_Wlo[768 * 256];
__device__ __nv_bfloat16 g_Wphi[256 * 256], g_Wplo[256 * 256];
__device__ __nv_bfloat16 g_Xhi[(size_t)NTOK * 256], g_Xlo[(size_t)NTOK * 256];
__device__ __nv_bfloat16 g_Uhi[(size_t)NTOK * 256], g_Ulo[(size_t)NTOK * 256];

// ---------------- helpers ------------------------------------------------------
__device__ __forceinline__ uint32_t smem_u32(const void* p) {
    return (uint32_t)__cvta_generic_to_shared(p);
}
__device__ __forceinline__ unsigned short f2bf_us(float v) {
    __nv_bfloat16 b = __float2bfloat16(v);
    return *reinterpret_cast<unsigned short*>(&b);
}
__device__ __forceinline__ void cp_async16(uint32_t s, const void* g) {
    asm volatile("cp.async.cg.shared.global [%0], [%1], 16;" :: "r"(s), "l"(g));
}
__device__ __forceinline__ void cp_commit() {
    asm volatile("cp.async.commit_group;");
}
__device__ __forceinline__ void ldsm_x4(uint32_t* r, uint32_t a) {
    asm volatile("ldmatrix.sync.aligned.m8n8.x4.shared.b16 {%0,%1,%2,%3}, [%4];"
                 : "=r"(r[0]), "=r"(r[1]), "=r"(r[2]), "=r"(r[3]) : "r"(a));
}
__device__ __forceinline__ void ldsm_x2(uint32_t* r, uint32_t a) {
    asm volatile("ldmatrix.sync.aligned.m8n8.x2.shared.b16 {%0,%1}, [%2];"
                 : "=r"(r[0]), "=r"(r[1]) : "r"(a));
}
__device__ __forceinline__ void mma_bf16(float* c, const uint32_t* a, const uint32_t* b) {
    asm volatile(
        "mma.sync.aligned.m16n8k16.row.col.f32.bf16.bf16.f32 "
        "{%0,%1,%2,%3}, {%4,%5,%6,%7}, {%8,%9}, {%0,%1,%2,%3};"
        : "+f"(c[0]), "+f"(c[1]), "+f"(c[2]), "+f"(c[3])
        : "r"(a[0]), "r"(a[1]), "r"(a[2]), "r"(a[3]), "r"(b[0]), "r"(b[1]));
}

// ---------------- W -> bf16 hi/lo (K-major already) ---------------------------
__global__ void convert_w_kernel(const float* __restrict__ wq, const float* __restrict__ wk,
                                 const float* __restrict__ wv, const float* __restrict__ wp) {
    int i = blockIdx.x * 256 + threadIdx.x;  // 0..262143
    float v;
    __nv_bfloat16 *hi, *lo;
    int o;
    if (i < 65536)        { v = wq[i];          o = i;          hi = g_Whi;  lo = g_Wlo; }
    else if (i < 131072)  { v = wk[i - 65536];  o = i;          hi = g_Whi;  lo = g_Wlo; }
    else if (i < 196608)  { v = wv[i - 131072]; o = i;          hi = g_Whi;  lo = g_Wlo; }
    else                  { v = wp[i - 196608]; o = i - 196608; hi = g_Wphi; lo = g_Wplo; }
    __nv_bfloat16 h = __float2bfloat16(v);
    hi[o] = h;
    lo[o] = __float2bfloat16(v - __bfloat162float(h));
}

// ---------------- transpose [c][hw] fp32 -> token-major bf16 hi/lo -------------
__global__ void transpose_convert_kernel(const float* __restrict__ src, int c_stride, int b_stride,
                                         __nv_bfloat16* __restrict__ dhi,
                                         __nv_bfloat16* __restrict__ dlo) {
    __shared__ float t[32][33];
    const int hw0 = blockIdx.x * 32, c0 = blockIdx.y * 32, b = blockIdx.z;
    const int tid = threadIdx.x;
    const int rl = tid >> 3, q = tid & 7;
    float4 v = *(const float4*)(src + (size_t)b * b_stride + (size_t)(c0 + rl) * c_stride + hw0 + q * 4);
    t[rl][q * 4 + 0] = v.x; t[rl][q * 4 + 1] = v.y;
    t[rl][q * 4 + 2] = v.z; t[rl][q * 4 + 3] = v.w;
    __syncthreads();
    const int n = b * HWN + hw0 + rl;
    ushort4 hs, ls;
    float f0 = t[q * 4 + 0][rl], f1 = t[q * 4 + 1][rl];
    float f2 = t[q * 4 + 2][rl], f3 = t[q * 4 + 3][rl];
    hs.x = f2bf_us(f0); hs.y = f2bf_us(f1); hs.z = f2bf_us(f2); hs.w = f2bf_us(f3);
    ls.x = f2bf_us(f0 - __bfloat162float(__float2bfloat16(f0)));
    ls.y = f2bf_us(f1 - __bfloat162float(__float2bfloat16(f1)));
    ls.z = f2bf_us(f2 - __bfloat162float(__float2bfloat16(f2)));
    ls.w = f2bf_us(f3 - __bfloat162float(__float2bfloat16(f3)));
    *(ushort4*)(dhi + (size_t)n * 256 + c0 + q * 4) = hs;
    *(ushort4*)(dlo + (size_t)n * 256 + c0 + q * 4) = ls;
}

// ---------------- mma.sync GEMM + fused GN stats partials ----------------------
// Shared-tile split: per K-chunk load Ahi/Alo/Bhi/Blo once, run 3 mma passes
// (Ahi*Bhi, Ahi*Blo, Alo*Bhi). 8 chunks of 32. Dynamic smem 80KB (2 stages).
__global__ __launch_bounds__(256) void mma_gemm_kernel(
    const __nv_bfloat16* __restrict__ Ahi, const __nv_bfloat16* __restrict__ Alo,
    const __nv_bfloat16* __restrict__ Bhi, const __nv_bfloat16* __restrict__ Blo,
    float* __restrict__ out, const float* __restrict__ bias, int gemm_id) {
    extern __shared__ __nv_bfloat16 smT[];   // [2 buf][4 mat][128*LDT]
    __shared__ float sred[8][4];
    const int tid = threadIdx.x;
    const int lane = tid & 31;
    const int wid = tid >> 5;
    const int wm = wid >> 2;          // 0..1
    const int wn = wid & 3;           // 0..3
    const int m0 = blockIdx.y * 128;
    const int n0 = blockIdx.x * 128;

    float acc[4][4][4];
#pragma unroll
    for (int i = 0; i < 4; i++)
#pragma unroll
        for (int j = 0; j < 4; j++)
#pragma unroll
            for (int r = 0; r < 4; r++) acc[i][j][r] = 0.f;

    const int lrow = tid >> 1;
    const int lch2 = (tid & 1) * 2;

#define TILE_BASE(buf, mat) (smT + ((buf) * 4 + (mat)) * (128 * LDT))
#define LOAD_STAGE(buf, kc)                                                             \
    do {                                                                                \
        const int k0 = (kc) * 32;                                                       \
        _Pragma("unroll")                                                               \
        for (int mat = 0; mat < 4; mat++) {                                             \
            const __nv_bfloat16* src =                                                  \
                ((mat == 0) ? Ahi : (mat == 1) ? Alo : (mat == 2) ? Bhi : Blo) +        \
                (size_t)(((mat < 2) ? m0 : n0) + lrow) * 256 + k0 + lch2 * 8;           \
            uint32_t d = smem_u32(TILE_BASE(buf, mat) + lrow * LDT + lch2 * 8);         \
            cp_async16(d, src);                                                         \
            cp_async16(d + 16, src + 8);                                                \
        }                                                                               \
        cp_commit();                                                                    \
    } while (0)

    LOAD_STAGE(0, 0);

    int buf = 0;
    for (int kc = 0; kc < 8; kc++) {
        if (kc + 1 < 8) {
            LOAD_STAGE(buf ^ 1, kc + 1);
            asm volatile("cp.async.wait_group 1;");
        } else {
            asm volatile("cp.async.wait_group 0;");
        }
        __syncthreads();

#pragma unroll
        for (int pass = 0; pass < 3; pass++) {
            const __nv_bfloat16* At = TILE_BASE(buf, (pass == 2) ? 1 : 0);
            const __nv_bfloat16* Bt = TILE_BASE(buf, (pass == 1) ? 3 : 2);
#pragma unroll
            for (int ks = 0; ks < 2; ks++) {
                uint32_t afr[4][4];
#pragma unroll
                for (int i = 0; i < 4; i++) {
                    uint32_t a = smem_u32(&At[(wm * 64 + i * 16 + (lane & 15)) * LDT +
                                             ((lane >> 4) * 8 + ks * 16)]);
                    ldsm_x4(afr[i], a);
                }
                uint32_t bfr[4][2];
#pragma unroll
                for (int j = 0; j < 4; j++) {
                    int l2 = lane & 15;
                    uint32_t a = smem_u32(&Bt[(wn * 32 + j * 8 + (l2 & 7)) * LDT +
                                             (((l2 >> 3) & 1) * 8 + ks * 16)]);
                    ldsm_x2(bfr[j], a);
                }
#pragma unroll
                for (int i = 0; i < 4; i++)
#pragma unroll
                    for (int j = 0; j < 4; j++) mma_bf16(acc[i][j], afr[i], bfr[j]);
            }
        }
        __syncthreads();
        buf ^= 1;
    }
#undef LOAD_STAGE
#undef TILE_BASE

    float s[2] = {0.f, 0.f}, s2[2] = {0.f, 0.f};
#pragma unroll
    for (int i = 0; i < 4; i++) {
        const int row = m0 + wm * 64 + i * 16 + (lane >> 2);
        const int gh = i >> 1;
        const float b0v = bias ? bias[row] : 0.f;
        const float b1v = bias ? bias[row + 8] : 0.f;
#pragma unroll
        for (int j = 0; j < 4; j++) {
            const int col = n0 + wn * 32 + j * 8 + (lane & 3) * 2;
            float v0x = acc[i][j][0] + b0v, v0y = acc[i][j][1] + b0v;
            float v1x = acc[i][j][2] + b1v, v1y = acc[i][j][3] + b1v;
            s[gh] += (v0x + v0y) + (v1x + v1y);
            s2[gh] += v0x * v0x + v0y * v0y + v1x * v1x + v1y * v1y;
            *(float2*)(out + (size_t)row * NTOK + col) = make_float2(v0x, v0y);
            *(float2*)(out + (size_t)(row + 8) * NTOK + col) = make_float2(v1x, v1y);
        }
    }

    int slot = (gemm_id == 0) ? ((blockIdx.y < 4) ? (int)(blockIdx.y >> 1) : -1) : 2;
    if (slot < 0) return;
    const int group_base = (gemm_id == 0) ? (blockIdx.y & 1) * 4 : blockIdx.y * 4;

#pragma unroll
    for (int off = 16; off > 0; off >>= 1) {
        s[0] += __shfl_xor_sync(0xffffffffu, s[0], off);
        s[1] += __shfl_xor_sync(0xffffffffu, s[1], off);
        s2[0] += __shfl_xor_sync(0xffffffffu, s2[0], off);
        s2[1] += __shfl_xor_sync(0xffffffffu, s2[1], off);
    }
    if (lane == 0) {
        sred[wid][0] = s[0]; sred[wid][1] = s[1];
        sred[wid][2] = s2[0]; sred[wid][3] = s2[1];
    }
    __syncthreads();
    if (tid < 4) {
        const int wmm = tid >> 1, gh = tid & 1;
        float ss = 0.f, ss2 = 0.f;
#pragma unroll
        for (int w = 0; w < 4; w++) {
            ss += sred[wmm * 4 + w][gh];
            ss2 += sred[wmm * 4 + w][2 + gh];
        }
        const int b = blockIdx.x >> 5;
        const int bxl = blockIdx.x & 31;
        const int pair = b * 8 + group_base + wmm * 2 + gh;
        g_part[slot][pair][bxl][0] = ss;
        g_part[slot][pair][bxl][1] = ss2;
    }
}

// ---------------- fused depthwise conv 3x3 + GeLU + conv 3x3 -------------------
__global__ __launch_bounds__(256) void dwconv_fused_kernel(
    const float* __restrict__ x,
    const float* __restrict__ dw1, const float* __restrict__ db1,
    const float* __restrict__ dw2, const float* __restrict__ db2) {
    __shared__ float xs[64 * 64];
    __shared__ float p1[64 * 65];
    const int bc = blockIdx.x;          // b*256 + c
    const int c = bc & 255;
    const float* xb = x + (size_t)bc * HWN;
    const int tid = threadIdx.x;

#pragma unroll
    for (int i = 0; i < 4; i++) {
        int idx = tid + i * 256;
        *(float4*)&xs[idx * 4] = *(const float4*)(xb + idx * 4);
    }
    float w1[9], w2[9];
#pragma unroll
    for (int i = 0; i < 9; i++) { w1[i] = dw1[c * 9 + i]; w2[i] = dw2[c * 9 + i]; }
    const float b1 = db1[c], b2 = db2[c];
    __syncthreads();

#pragma unroll
    for (int i = 0; i < 16; i++) {
        int idx = tid + i * 256;
        int px = idx & 63, py = idx >> 6;
        float acc = b1;
#pragma unroll
        for (int dy = -1; dy <= 1; dy++) {
            int yy = py + dy;
            if ((unsigned)yy > 63u) continue;
#pragma unroll
            for (int dx = -1; dx <= 1; dx++) {
                int xx = px + dx;
                if ((unsigned)xx > 63u) continue;
                acc = fmaf(xs[yy * 64 + xx], w1[(dy + 1) * 3 + (dx + 1)], acc);
            }
        }
        p1[py * 65 + px] = 0.5f * acc * (1.f + erff(acc * 0.70710678118654752f));
    }
    __syncthreads();

#pragma unroll
    for (int i = 0; i < 16; i++) {
        int idx = tid + i * 256;
        int px = idx & 63, py = idx >> 6;
        float acc = b2;
#pragma unroll
        for (int dy = -1; dy <= 1; dy++) {
            int yy = py + dy;
            if ((unsigned)yy > 63u) continue;
#pragma unroll
            for (int dx = -1; dx <= 1; dx++) {
                int xx = px + dx;
                if ((unsigned)xx > 63u) continue;
                acc = fmaf(p1[yy * 65 + xx], w2[(dy + 1) * 3 + (dx + 1)], acc);
            }
        }
        g_pos[(size_t)bc * HWN + idx] = acc;
    }
}

// ---------------- attention via moment expansion + residual + bf16 emission ----
// Stats finalization folded in (16 warps reduce 16 (slot,head) pairs at start).
__global__ __launch_bounds__(1024) void attn_kernel(
    const float* __restrict__ gqg, const float* __restrict__ gqb,
    const float* __restrict__ gkg, const float* __restrict__ gkb) {
    extern __shared__ float smf[];
    __shared__ float sstat[2][8][2];  // [slot q/k][head][mean,rstd]
    float* smq = smf;                 // [256][33]
    float* smk = smf + 256 * 33;
    float* smv = smf + 2 * 256 * 33;
    float* smp = smf + 3 * 256 * 33;  // pos tile
    const int tid = threadIdx.x;
    const int warp = tid >> 5;
    const int lane = tid & 31;
    const int n0 = blockIdx.x * 32;
    const int b = n0 >> 12;
    const int hw0 = n0 & 4095;

    if (warp < 16) {
        const int sl = warp >> 3;
        const int h = warp & 7;
        float s = g_part[sl][b * 8 + h][lane][0];
        float s2 = g_part[sl][b * 8 + h][lane][1];
#pragma unroll
        for (int off = 16; off > 0; off >>= 1) {
            s += __shfl_xor_sync(0xffffffffu, s, off);
            s2 += __shfl_xor_sync(0xffffffffu, s2, off);
        }
        if (lane == 0) {
            const float inv = 1.f / 131072.f;
            float mean = s * inv;
            float var = s2 * inv - mean * mean;
            sstat[sl][h][0] = mean;
            sstat[sl][h][1] = rsqrtf(var + EPS_GN);
        }
    }

#pragma unroll
    for (int r = 0; r < 6; r++) {
        const int tens = r >> 1;
        const int slot = tid + r * 1024;
        const int row = (slot >> 3) & 255;
        const int q8 = slot & 7;
        float4 v = *(const float4*)(g_Y + (size_t)(tens * 256 + row) * NTOK + n0 + q8 * 4);
        float* dst = smf + tens * (256 * 33) + row * 33 + q8 * 4;
        dst[0] = v.x; dst[1] = v.y; dst[2] = v.z; dst[3] = v.w;
    }
#pragma unroll
    for (int r = 0; r < 2; r++) {
        const int slot = tid + r * 1024;
        const int row = (slot >> 3) & 255;
        const int q8 = slot & 7;
        float4 v = *(const float4*)(g_pos + (size_t)b * CHW + (size_t)row * HWN + hw0 + q8 * 4);
        float* dst = smp + row * 33 + q8 * 4;
        dst[0] = v.x; dst[1] = v.y; dst[2] = v.z; dst[3] = v.w;
    }
    __syncthreads();

    const float scale = 0.17677669529663687f;  // 1/sqrt(32)
    float oacc[8];
#pragma unroll 1
    for (int h = 0; h < 8; h++) {
        const int c = h * 32 + lane;
        float q = smq[c * 33 + warp];
        float k = smk[c * 33 + warp];
        float vv = smv[c * 33 + warp];
        q = (q - sstat[0][h][0]) * sstat[0][h][1] * gqg[c] + gqb[c];
        k = (k - sstat[1][h][0]) * sstat[1][h][1] * gkg[c] + gkb[c];
        float sq = q * q, sk = k * k;
#pragma unroll
        for (int off = 16; off > 0; off >>= 1) {
            sq += __shfl_xor_sync(0xffffffffu, sq, off);
            sk += __shfl_xor_sync(0xffffffffu, sk, off);
        }
        const float qn = q / fmaxf(sqrtf(sq), 1e-12f);
        const float kn = k / fmaxf(sqrtf(sk), 1e-12f);
        const float s = qn * scale;

        const float k2 = kn * kn;
        const float k3 = k2 * kn;
        const float k4 = k2 * k2;
        float a1 = kn, a2 = k2, a3 = k3, a4 = k4;
        float b0 = vv, b1m = kn * vv, b2 = k2 * vv, b3 = k3 * vv, b4 = k4 * vv;
#pragma unroll
        for (int off = 16; off > 0; off >>= 1) {
            a1 += __shfl_xor_sync(0xffffffffu, a1, off);
            a2 += __shfl_xor_sync(0xffffffffu, a2, off);
            a3 += __shfl_xor_sync(0xffffffffu, a3, off);
            a4 += __shfl_xor_sync(0xffffffffu, a4, off);
            b0 += __shfl_xor_sync(0xffffffffu, b0, off);
            b1m += __shfl_xor_sync(0xffffffffu, b1m, off);
            b2 += __shfl_xor_sync(0xffffffffu, b2, off);
            b3 += __shfl_xor_sync(0xffffffffu, b3, off);
            b4 += __shfl_xor_sync(0xffffffffu, b4, off);
        }
        const float c2 = 0.5f, c3 = 1.f / 6.f, c4 = 1.f / 24.f;
        float num = fmaf(s, fmaf(s, fmaf(s, fmaf(s, b4 * c4, b3 * c3), b2 * c2), b1m), b0);
        float den = fmaf(s, fmaf(s, fmaf(s, fmaf(s, a4 * c4, a3 * c3), a2 * c2), a1), 32.f);
        oacc[h] = __fdividef(num, den) + smp[c * 33 + warp];
    }
#pragma unroll
    for (int h = 0; h < 8; h++) smq[(h * 32 + lane) * 33 + warp] = oacc[h];
    __syncthreads();

#pragma unroll
    for (int it = 0; it < 2; it++) {
        const int j = (tid >> 6) + it * 16;   // token 0..31
        const int c0 = (tid & 63) * 4;
        float f0 = smq[(c0 + 0) * 33 + j];
        float f1 = smq[(c0 + 1) * 33 + j];
        float f2 = smq[(c0 + 2) * 33 + j];
        float f3 = smq[(c0 + 3) * 33 + j];
        ushort4 hs, ls;
        hs.x = f2bf_us(f0); hs.y = f2bf_us(f1); hs.z = f2bf_us(f2); hs.w = f2bf_us(f3);
        ls.x = f2bf_us(f0 - __bfloat162float(__float2bfloat16(f0)));
        ls.y = f2bf_us(f1 - __bfloat162float(__float2bfloat16(f1)));
        ls.z = f2bf_us(f2 - __bfloat162float(__float2bfloat16(f2)));
        ls.w = f2bf_us(f3 - __bfloat162float(__float2bfloat16(f3)));
        const size_t n = (size_t)(n0 + j);
        *(ushort4*)(g_Uhi + n * 256 + c0) = hs;
        *(ushort4*)(g_Ulo + n * 256 + c0) = ls;
    }
}

// ---------------- final GN apply (stats reduced in-block) ----------------------
__global__ void gn_apply_kernel(const float* __restrict__ gamma,
                                const float* __restrict__ beta,
                                float* __restrict__ out) {
    __shared__ float sms[2];
    const int blk0 = blockIdx.x * 256;
    const int cB = blk0 >> 12;
    const int bB = ((blk0 & 4095) * 4) >> 12;
    if (threadIdx.x < 32) {
        const int lane = threadIdx.x;
        const int pair = bB * 8 + (cB >> 5);
        float s = g_part[2][pair][lane][0];
        float s2 = g_part[2][pair][lane][1];
#pragma unroll
        for (int off = 16; off > 0; off >>= 1) {
            s += __shfl_xor_sync(0xffffffffu, s, off);
            s2 += __shfl_xor_sync(0xffffffffu, s2, off);
        }
        if (lane == 0) {
            const float inv = 1.f / 131072.f;
            float mean = s * inv;
            float var = s2 * inv - mean * mean;
            sms[0] = mean;
            sms[1] = rsqrtf(var + EPS_GN);
        }
    }
    __syncthreads();
    const int idx4 = blk0 + threadIdx.x;
    const int c = idx4 >> 12;
    const int n = (idx4 & 4095) * 4;
    const int b = n >> 12;
    const float mean = sms[0], rstd = sms[1];
    const float ga = gamma[c], be = beta[c];
    float4 v = *(const float4*)(g_Z + (size_t)idx4 * 4);
    v.x = (v.x - mean) * rstd * ga + be;
    v.y = (v.y - mean) * rstd * ga + be;
    v.z = (v.z - mean) * rstd * ga + be;
    v.w = (v.w - mean) * rstd * ga + be;
    *(float4*)(out + (size_t)b * CHW + (size_t)c * HWN + (n & 4095)) = v;
}

// ---------------- launcher -----------------------------------------------------
extern "C" void kernel_launch(void* const* d_in, const int* in_sizes, int n_in,
                              void* d_out, int out_size) {
    const float* x        = (const float*)d_in[0];
    const float* wq       = (const float*)d_in[1];
    const float* gq_gamma = (const float*)d_in[2];
    const float* gq_beta  = (const float*)d_in[3];
    const float* wk       = (const float*)d_in[4];
    const float* gk_gamma = (const float*)d_in[5];
    const float* gk_beta  = (const float*)d_in[6];
    const float* wv       = (const float*)d_in[7];
    const float* wp       = (const float*)d_in[8];
    const float* bp       = (const float*)d_in[9];
    const float* gp_gamma = (const float*)d_in[10];
    const float* gp_beta  = (const float*)d_in[11];
    const float* dw1      = (const float*)d_in[12];
    const float* db1      = (const float*)d_in[13];
    const float* dw2      = (const float*)d_in[14];
    const float* db2      = (const float*)d_in[15];
    float* out = (float*)d_out;

    const int GEMM_SMEM = 2 * 4 * 128 * LDT * 2;  // 81920 bytes
    static bool attr_set = false;
    if (!attr_set) {
        cudaFuncSetAttribute(attn_kernel, cudaFuncAttributeMaxDynamicSharedMemorySize, 135168);
        cudaFuncSetAttribute(mma_gemm_kernel, cudaFuncAttributeMaxDynamicSharedMemorySize, GEMM_SMEM);
        attr_set = true;
    }

    float *g_Y_p, *g_Z_p;
    __nv_bfloat16 *whi, *wlo, *wphi, *wplo, *xhi, *xlo, *uhi, *ulo;
    cudaGetSymbolAddress((void**)&g_Y_p, g_Y);
    cudaGetSymbolAddress((void**)&g_Z_p, g_Z);
    cudaGetSymbolAddress((void**)&whi, g_Whi);
    cudaGetSymbolAddress((void**)&wlo, g_Wlo);
    cudaGetSymbolAddress((void**)&wphi, g_Wphi);
    cudaGetSymbolAddress((void**)&wplo, g_Wplo);
    cudaGetSymbolAddress((void**)&xhi, g_Xhi);
    cudaGetSymbolAddress((void**)&xlo, g_Xlo);
    cudaGetSymbolAddress((void**)&uhi, g_Uhi);
    cudaGetSymbolAddress((void**)&ulo, g_Ulo);

    // 1. weight + input conversion
    convert_w_kernel<<<1024, 256>>>(wq, wk, wv, wp);
    transpose_convert_kernel<<<dim3(128, 8, BATCH), 256>>>(x, HWN, CHW, xhi, xlo);
    // 2. QKV GEMM (stats for q,k fused into epilogue) -> g_Y [768][16384]
    mma_gemm_kernel<<<dim3(128, 6), 256, GEMM_SMEM>>>(whi, wlo, xhi, xlo, g_Y_p, nullptr, 0);
    // 3. fused positional path -> g_pos
    dwconv_fused_kernel<<<1024, 256>>>(x, dw1, db1, dw2, db2);
    // 4. attention (finalizes q/k stats in-block) + residual -> U bf16 hi/lo
    attn_kernel<<<512, 1024, 135168>>>(gq_gamma, gq_beta, gk_gamma, gk_beta);
    // 5. output projection GEMM (stats fused) -> g_Z [256][16384]
    mma_gemm_kernel<<<dim3(128, 2), 256, GEMM_SMEM>>>(wphi, wplo, uhi, ulo, g_Z_p, bp, 1);
    // 6. final group norm apply (finalizes z stats in-block)
    gn_apply_kernel<<<NTOK * 256 / 1024, 256>>>(gp_gamma, gp_beta, out);
}